// round 1
// baseline (speedup 1.0000x reference)
#include <cuda_runtime.h>
#include <math.h>

#define HH 512
#define WW 512
#define NP (HH*WW)

// ---------------- scratch (device globals; no allocations allowed) --------
__device__ float g_x[NP*64];              // input in NHWC
__device__ float g_h1[NP*64];             // layer-1 output, NHWC
__device__ float g_off[NP*18];            // offsets, [pixel][18]
__device__ float g_wdcnT[2][9*64*64];     // dcn weights: [tap][cin][cout]
__device__ float g_woffT[2][9*64*18];     // offset-conv weights: [tap][cin][cout]
__device__ float g_bnscale[2][64];
__device__ float g_bnshift[2][64];

// ---------------- prep: weight transform + BN folding ---------------------
__global__ void prep_kernel(
    const float* __restrict__ w1o, const float* __restrict__ w2o,
    const float* __restrict__ wd1, const float* __restrict__ wd2,
    const float* __restrict__ db1, const float* __restrict__ db2,
    const float* __restrict__ g1, const float* __restrict__ b1,
    const float* __restrict__ m1, const float* __restrict__ v1,
    const float* __restrict__ g2, const float* __restrict__ b2,
    const float* __restrict__ m2, const float* __restrict__ v2)
{
    int idx = blockIdx.x * blockDim.x + threadIdx.x;
    int nth = gridDim.x * blockDim.x;
    for (int i = idx; i < 9*64*64; i += nth) {
        int k = i / 4096, r = i & 4095;
        int c = r >> 6, oc = r & 63;
        int src = (oc*64 + c)*9 + k;     // OIHW, tap-minor
        g_wdcnT[0][i] = wd1[src];
        g_wdcnT[1][i] = wd2[src];
    }
    for (int i = idx; i < 9*64*18; i += nth) {
        int k = i / 1152, r = i % 1152;
        int c = r / 18, oc = r % 18;
        int src = (oc*64 + c)*9 + k;
        g_woffT[0][i] = w1o[src];
        g_woffT[1][i] = w2o[src];
    }
    if (idx < 64) {
        float s = g1[idx] * rsqrtf(v1[idx] + 1e-5f);
        g_bnscale[0][idx] = s;
        g_bnshift[0][idx] = b1[idx] - m1[idx]*s + db1[idx]*s;
        float s2 = g2[idx] * rsqrtf(v2[idx] + 1e-5f);
        g_bnscale[1][idx] = s2;
        g_bnshift[1][idx] = b2[idx] - m2[idx]*s2 + db2[idx]*s2;
    }
}

// ---------------- NCHW -> NHWC transpose ----------------------------------
__global__ void __launch_bounds__(256) transpose_kernel(const float* __restrict__ x) {
    __shared__ float tile[64][65];
    int p0 = blockIdx.x * 64;
    int t = threadIdx.x;
    #pragma unroll
    for (int i = 0; i < 16; i++) {
        int idx = i*256 + t;
        int c = idx >> 6, pl = idx & 63;
        tile[c][pl] = x[c*NP + p0 + pl];
    }
    __syncthreads();
    #pragma unroll
    for (int i = 0; i < 16; i++) {
        int idx = i*256 + t;
        int pl = idx >> 6, c = idx & 63;
        g_x[(p0 + pl)*64 + c] = tile[c][pl];
    }
}

// ---------------- offset conv: 3x3, 64 -> 18, pad 1 ------------------------
// Tile: 128 pixels (one row segment) x 18 outputs, K = 9 taps x 64 ch.
__global__ void __launch_bounds__(256) offconv_kernel(int layer, const float* __restrict__ bias) {
    __shared__ float A_s[64*20];    // [cin][oc pad 20]
    __shared__ float S[64*132];     // [cin][px pad 132]
    const float* __restrict__ in = layer ? g_h1 : g_x;
    const float* __restrict__ wT = g_woffT[layer];
    int t = threadIdx.x;
    int by = blockIdx.x >> 2;
    int x0 = (blockIdx.x & 3) * 128;
    int spx = t & 127, shp = t >> 7, c0 = shp * 32;
    int px_t = t & 31, oc_t = t >> 5;
    int px0 = px_t * 4;
    float acc[3][4] = {};
    for (int k = 0; k < 9; k++) {
        int ky = k/3 - 1, kx = k%3 - 1;
        __syncthreads();
        for (int i = t; i < 1152; i += 256) {
            int c = i / 18, oc = i % 18;
            A_s[c*20 + oc] = wT[k*1152 + i];
        }
        {
            int yy = by + ky, xx = x0 + spx + kx;
            if (yy >= 0 && yy < HH && xx >= 0 && xx < WW) {
                const float4* sp = (const float4*)(in + ((size_t)(yy*WW + xx))*64 + c0);
                #pragma unroll
                for (int j = 0; j < 8; j++) {
                    float4 v = sp[j];
                    S[(c0 + j*4 + 0)*132 + spx] = v.x;
                    S[(c0 + j*4 + 1)*132 + spx] = v.y;
                    S[(c0 + j*4 + 2)*132 + spx] = v.z;
                    S[(c0 + j*4 + 3)*132 + spx] = v.w;
                }
            } else {
                #pragma unroll
                for (int j = 0; j < 32; j++) S[(c0 + j)*132 + spx] = 0.f;
            }
        }
        __syncthreads();
        #pragma unroll 8
        for (int c = 0; c < 64; c++) {
            float4 b4 = *(const float4*)(S + c*132 + px0);
            #pragma unroll
            for (int j = 0; j < 3; j++) {
                float a = A_s[c*20 + oc_t*3 + j];
                acc[j][0] += a * b4.x;
                acc[j][1] += a * b4.y;
                acc[j][2] += a * b4.z;
                acc[j][3] += a * b4.w;
            }
        }
    }
    int p0 = by*WW + x0 + px0;
    #pragma unroll
    for (int j = 0; j < 3; j++) {
        int oc = oc_t*3 + j;
        if (oc < 18) {
            float bb = bias[oc];
            #pragma unroll
            for (int i = 0; i < 4; i++)
                g_off[(size_t)(p0 + i)*18 + oc] = acc[j][i] + bb;
        }
    }
}

// ---------------- deformable conv + BN + ReLU (+optional fused 1x1) -------
// Tile: 128 pixels x 64 out-ch. Per tap: bilinear-sample S[64c][128px], GEMM.
// Thread micro-tile: 8 oc x 4 px (conflict-free LDS.128 on both operands).
__device__ __forceinline__ void corner_fma(float sv[16], const float* __restrict__ base, float wgt) {
    const float4* p = (const float4*)base;
    #pragma unroll
    for (int j = 0; j < 4; j++) {
        float4 v = p[j];
        sv[4*j+0] += wgt*v.x; sv[4*j+1] += wgt*v.y;
        sv[4*j+2] += wgt*v.z; sv[4*j+3] += wgt*v.w;
    }
}

template<int FUSE>
__global__ void __launch_bounds__(256, 2) dcn_kernel(int layer,
    const float* __restrict__ w1x1, const float* __restrict__ b1x1,
    float* __restrict__ out_f)
{
    extern __shared__ float sm[];
    float* offs = sm;              // 2304 = 128*18
    float* bns  = sm + 2304;       // 128 (scale 64 | shift 64)
    float* A_s  = sm + 2432;       // 4096 = [cin][oc]
    float* S    = sm + 6528;       // 8448 = [cin][px pad 132]
    float* red  = sm + 14976;      // 1024 (FUSE only)
    const float* __restrict__ in  = layer ? g_h1 : g_x;
    const float* __restrict__ wT  = g_wdcnT[layer];
    const float* __restrict__ scl = g_bnscale[layer];
    const float* __restrict__ shf = g_bnshift[layer];
    int t = threadIdx.x;
    int by = blockIdx.x >> 2;
    int x0 = (blockIdx.x & 3) * 128;
    int p0 = by*WW + x0;
    for (int i = t; i < 2304; i += 256) offs[i] = g_off[(size_t)p0*18 + i];
    if (t < 64) { bns[t] = scl[t]; bns[64 + t] = shf[t]; }
    int spx = t & 127, shp = t >> 7, c0 = shp * 32;
    int px_t = t & 31, oc_t = t >> 5;
    int px0 = px_t * 4, oc0 = oc_t * 8;
    float acc[8][4] = {};
    for (int k = 0; k < 9; k++) {
        __syncthreads();
        // stage this tap's weights [cin][oc] (contiguous copy)
        #pragma unroll
        for (int i = 0; i < 16; i++) A_s[i*256 + t] = wT[k*4096 + i*256 + t];
        // build sampled tile
        {
            float dy = offs[spx*18 + 2*k];
            float dx = offs[spx*18 + 2*k + 1];
            float py  = (float)(by + k/3 - 1) + dy;
            float pxf = (float)(x0 + spx + k%3 - 1) + dx;
            float fy = floorf(py), fx = floorf(pxf);
            float wy = py - fy, wx = pxf - fx;
            int yi = (int)fy, xi = (int)fx;
            float w00 = (1.f - wy)*(1.f - wx);
            float w01 = (1.f - wy)*wx;
            float w10 = wy*(1.f - wx);
            float w11 = wy*wx;
            bool vy0 = (yi   >= 0) && (yi   < HH);
            bool vy1 = (yi+1 >= 0) && (yi+1 < HH);
            bool vx0 = (xi   >= 0) && (xi   < WW);
            bool vx1 = (xi+1 >= 0) && (xi+1 < WW);
            #pragma unroll
            for (int ch = 0; ch < 2; ch++) {
                int cb = c0 + ch*16;
                float sv[16];
                #pragma unroll
                for (int j = 0; j < 16; j++) sv[j] = 0.f;
                if (vy0 && vx0) corner_fma(sv, in + ((size_t)( yi   *WW + xi  ))*64 + cb, w00);
                if (vy0 && vx1) corner_fma(sv, in + ((size_t)( yi   *WW + xi+1))*64 + cb, w01);
                if (vy1 && vx0) corner_fma(sv, in + ((size_t)((yi+1)*WW + xi  ))*64 + cb, w10);
                if (vy1 && vx1) corner_fma(sv, in + ((size_t)((yi+1)*WW + xi+1))*64 + cb, w11);
                #pragma unroll
                for (int j = 0; j < 16; j++) S[(cb + j)*132 + spx] = sv[j];
            }
        }
        __syncthreads();
        // GEMM accumulate: acc[8oc][4px] += A_s[c][oc] * S[c][px]
        #pragma unroll 8
        for (int c = 0; c < 64; c++) {
            float4 a0 = *(const float4*)(A_s + c*64 + oc0);
            float4 a1 = *(const float4*)(A_s + c*64 + oc0 + 4);
            float4 b  = *(const float4*)(S + c*132 + px0);
            float av[8] = {a0.x,a0.y,a0.z,a0.w,a1.x,a1.y,a1.z,a1.w};
            float bv[4] = {b.x,b.y,b.z,b.w};
            #pragma unroll
            for (int j = 0; j < 8; j++)
                #pragma unroll
                for (int i = 0; i < 4; i++)
                    acc[j][i] += av[j]*bv[i];
        }
    }
    // epilogue: BN + ReLU
    float vals[8][4];
    #pragma unroll
    for (int j = 0; j < 8; j++) {
        float s = bns[oc0 + j], h = bns[64 + oc0 + j];
        #pragma unroll
        for (int i = 0; i < 4; i++) {
            float v = acc[j][i]*s + h;
            vals[j][i] = v > 0.f ? v : 0.f;
        }
    }
    if (!FUSE) {
        #pragma unroll
        for (int i = 0; i < 4; i++) {
            size_t p = (size_t)(p0 + px0 + i);
            float4 o0 = make_float4(vals[0][i], vals[1][i], vals[2][i], vals[3][i]);
            float4 o1 = make_float4(vals[4][i], vals[5][i], vals[6][i], vals[7][i]);
            *(float4*)(g_h1 + p*64 + oc0)     = o0;
            *(float4*)(g_h1 + p*64 + oc0 + 4) = o1;
        }
    } else {
        // fused 1x1 conv: out[px] = sum_oc w[oc]*h[oc][px] + b
        float part[4] = {0.f, 0.f, 0.f, 0.f};
        #pragma unroll
        for (int j = 0; j < 8; j++) {
            float ww = w1x1[oc0 + j];
            #pragma unroll
            for (int i = 0; i < 4; i++) part[i] += vals[j][i]*ww;
        }
        #pragma unroll
        for (int i = 0; i < 4; i++) red[oc_t*128 + px0 + i] = part[i];
        __syncthreads();
        if (t < 128) {
            float s = b1x1[0];
            #pragma unroll
            for (int j = 0; j < 8; j++) s += red[j*128 + t];
            out_f[p0 + t] = s;
        }
    }
}

// ---------------- launch ---------------------------------------------------
extern "C" void kernel_launch(void* const* d_in, const int* in_sizes, int n_in,
                              void* d_out, int out_size) {
    const float* x    = (const float*)d_in[0];
    const float* w1o  = (const float*)d_in[1];
    const float* b1o  = (const float*)d_in[2];
    const float* wd1  = (const float*)d_in[3];
    const float* db1  = (const float*)d_in[4];
    const float* g1   = (const float*)d_in[5];
    const float* be1  = (const float*)d_in[6];
    const float* m1   = (const float*)d_in[7];
    const float* v1   = (const float*)d_in[8];
    const float* w2o  = (const float*)d_in[9];
    const float* b2o  = (const float*)d_in[10];
    const float* wd2  = (const float*)d_in[11];
    const float* db2  = (const float*)d_in[12];
    const float* g2   = (const float*)d_in[13];
    const float* be2  = (const float*)d_in[14];
    const float* m2   = (const float*)d_in[15];
    const float* v2   = (const float*)d_in[16];
    const float* wc   = (const float*)d_in[17];
    const float* bc   = (const float*)d_in[18];
    float* out = (float*)d_out;

    const int smem = 16000 * (int)sizeof(float);  // 64 KB -> opt-in
    cudaFuncSetAttribute(dcn_kernel<0>, cudaFuncAttributeMaxDynamicSharedMemorySize, smem);
    cudaFuncSetAttribute(dcn_kernel<1>, cudaFuncAttributeMaxDynamicSharedMemorySize, smem);

    prep_kernel<<<64, 256>>>(w1o, w2o, wd1, wd2, db1, db2,
                             g1, be1, m1, v1, g2, be2, m2, v2);
    transpose_kernel<<<NP/64, 256>>>(x);
    offconv_kernel<<<2048, 256>>>(0, b1o);
    dcn_kernel<0><<<2048, 256, smem>>>(0, nullptr, nullptr, nullptr);
    offconv_kernel<<<2048, 256>>>(1, b2o);
    dcn_kernel<1><<<2048, 256, smem>>>(1, wc, bc, out);
}

// round 3
// speedup vs baseline: 1.3809x; 1.3809x over previous
#include <cuda_runtime.h>
#include <cuda_bf16.h>
#include <math.h>
#include <stdint.h>

#define HH 512
#define WW 512
#define NP (HH*WW)

// ---------------- scratch (device globals) ---------------------------------
__device__ float g_x[NP*64];                                  // input NHWC f32
__device__ float g_h1[NP*64];                                 // layer-1 out NHWC f32
__device__ float g_off[NP*18];                                // offsets [px][18]
__device__ __align__(16) __nv_bfloat16 g_wdb[2][9][2][64*64]; // dcn W: [layer][tap][hi/lo][SWZ(c*128+oc*2)]
__device__ __align__(16) __nv_bfloat16 g_wob[2][9][2][64*64]; // off W padded to 64 oc
__device__ float g_bnscale[2][64];
__device__ float g_bnshift[2][64];

// ---------------- helpers ----------------------------------------------------
__device__ __forceinline__ uint32_t smem_u32(const void* p) {
    uint32_t a;
    asm("{ .reg .u64 t; cvta.to.shared.u64 t, %1; cvt.u32.u64 %0, t; }" : "=r"(a) : "l"(p));
    return a;
}
#define SWZ(b) ((b) ^ (((b) >> 3) & 0x70))

#define LDSM4(r, addr) \
    asm volatile("ldmatrix.sync.aligned.m8n8.x4.shared.b16 {%0,%1,%2,%3}, [%4];" \
        : "=r"((r)[0]), "=r"((r)[1]), "=r"((r)[2]), "=r"((r)[3]) : "r"(addr))
#define LDSM4T(r, addr) \
    asm volatile("ldmatrix.sync.aligned.m8n8.x4.trans.shared.b16 {%0,%1,%2,%3}, [%4];" \
        : "=r"((r)[0]), "=r"((r)[1]), "=r"((r)[2]), "=r"((r)[3]) : "r"(addr))
#define MMA(d, a, b0_, b1_) \
    asm volatile("mma.sync.aligned.m16n8k16.row.col.f32.bf16.bf16.f32 " \
        "{%0,%1,%2,%3}, {%4,%5,%6,%7}, {%8,%9}, {%0,%1,%2,%3};" \
        : "+f"((d)[0]), "+f"((d)[1]), "+f"((d)[2]), "+f"((d)[3]) \
        : "r"((a)[0]), "r"((a)[1]), "r"((a)[2]), "r"((a)[3]), "r"(b0_), "r"(b1_))

// bf16 hi/lo split of 8 f32 -> two uint4 (packed bf16x2)
__device__ __forceinline__ void split8(const float* v, uint4& hi, uint4& lo) {
    uint32_t h[4], l[4];
    #pragma unroll
    for (int i = 0; i < 4; i++) {
        float a = v[2*i], b = v[2*i+1];
        __nv_bfloat16 ha = __float2bfloat16(a);
        __nv_bfloat16 hb = __float2bfloat16(b);
        __nv_bfloat16 la = __float2bfloat16(a - __bfloat162float(ha));
        __nv_bfloat16 lb = __float2bfloat16(b - __bfloat162float(hb));
        h[i] = ((uint32_t)__bfloat16_as_ushort(hb) << 16) | (uint32_t)__bfloat16_as_ushort(ha);
        l[i] = ((uint32_t)__bfloat16_as_ushort(lb) << 16) | (uint32_t)__bfloat16_as_ushort(la);
    }
    hi = make_uint4(h[0], h[1], h[2], h[3]);
    lo = make_uint4(l[0], l[1], l[2], l[3]);
}

__device__ __forceinline__ void corner_fma16(float* sv, const float* __restrict__ base, float wgt) {
    const float4* p = (const float4*)base;
    #pragma unroll
    for (int j = 0; j < 4; j++) {
        float4 v = p[j];
        sv[4*j+0] += wgt*v.x; sv[4*j+1] += wgt*v.y;
        sv[4*j+2] += wgt*v.z; sv[4*j+3] += wgt*v.w;
    }
}

// ---------------- shared GEMM: one tap, 3-pass bf16 split -------------------
// A: [128px][64c] bf16, 128B rows, SW128; hi at sA, lo at sA+16384.
// B: [64c][64oc] bf16, 128B rows, SW128; hi at sB, lo at sB+8192.
// Warp (mwarp 0..3, nwarp 0..1) computes 32px x (NB*8)oc.
template<int NB>
__device__ __forceinline__ void gemm_tap(uint32_t sA, uint32_t sB, int lid,
                                         int mwarp, int nwarp, float acc[2][NB][4]) {
    #pragma unroll
    for (int kb = 0; kb < 4; kb++) {
        uint32_t ah[2][4], al[2][4];
        #pragma unroll
        for (int mb = 0; mb < 2; mb++) {
            int row = mwarp*32 + mb*16 + (lid & 15);
            uint32_t a = sA + SWZ((uint32_t)(row*128 + (kb*16 + (lid>>4)*8)*2));
            LDSM4(ah[mb], a);
            LDSM4(al[mb], a + 16384);
        }
        #pragma unroll
        for (int nb2 = 0; nb2 < NB/2; nb2++) {
            int k = kb*16 + (lid & 15);
            int n = nwarp*(NB*8) + nb2*16 + (lid>>4)*8;
            uint32_t b = sB + SWZ((uint32_t)(k*128 + n*2));
            uint32_t bh[4], bl[4];
            LDSM4T(bh, b);
            LDSM4T(bl, b + 8192);
            #pragma unroll
            for (int mb = 0; mb < 2; mb++) {
                MMA(acc[mb][2*nb2],   ah[mb], bh[0], bh[1]);
                MMA(acc[mb][2*nb2],   al[mb], bh[0], bh[1]);
                MMA(acc[mb][2*nb2],   ah[mb], bl[0], bl[1]);
                MMA(acc[mb][2*nb2+1], ah[mb], bh[2], bh[3]);
                MMA(acc[mb][2*nb2+1], al[mb], bh[2], bh[3]);
                MMA(acc[mb][2*nb2+1], ah[mb], bl[2], bl[3]);
            }
        }
    }
}

// ---------------- prep: weight split/swizzle + BN folding -------------------
__global__ void prep_kernel(
    const float* __restrict__ w1o, const float* __restrict__ w2o,
    const float* __restrict__ wd1, const float* __restrict__ wd2,
    const float* __restrict__ db1, const float* __restrict__ db2,
    const float* __restrict__ g1, const float* __restrict__ b1,
    const float* __restrict__ m1, const float* __restrict__ v1,
    const float* __restrict__ g2, const float* __restrict__ b2,
    const float* __restrict__ m2, const float* __restrict__ v2)
{
    int idx = blockIdx.x * blockDim.x + threadIdx.x;
    int nth = gridDim.x * blockDim.x;
    for (int i = idx; i < 2*9*64*64; i += nth) {
        int layer = i / 36864, r = i % 36864;
        int k = r / 4096, rr = r & 4095;
        int c = rr >> 6, oc = rr & 63;
        uint32_t sidx = SWZ((uint32_t)(c*128 + oc*2)) >> 1;
        {
            float val = (layer ? wd2 : wd1)[(oc*64 + c)*9 + k];
            __nv_bfloat16 hi = __float2bfloat16(val);
            __nv_bfloat16 lo = __float2bfloat16(val - __bfloat162float(hi));
            g_wdb[layer][k][0][sidx] = hi;
            g_wdb[layer][k][1][sidx] = lo;
        }
        {
            float val = (oc < 18) ? (layer ? w2o : w1o)[(oc*64 + c)*9 + k] : 0.f;
            __nv_bfloat16 hi = __float2bfloat16(val);
            __nv_bfloat16 lo = __float2bfloat16(val - __bfloat162float(hi));
            g_wob[layer][k][0][sidx] = hi;
            g_wob[layer][k][1][sidx] = lo;
        }
    }
    if (idx < 64) {
        float s = g1[idx] * rsqrtf(v1[idx] + 1e-5f);
        g_bnscale[0][idx] = s;
        g_bnshift[0][idx] = b1[idx] - m1[idx]*s + db1[idx]*s;
        float s2 = g2[idx] * rsqrtf(v2[idx] + 1e-5f);
        g_bnscale[1][idx] = s2;
        g_bnshift[1][idx] = b2[idx] - m2[idx]*s2 + db2[idx]*s2;
    }
}

// ---------------- NCHW -> NHWC ----------------------------------------------
__global__ void __launch_bounds__(256) transpose_kernel(const float* __restrict__ x) {
    __shared__ float tile[64][65];
    int p0 = blockIdx.x * 64;
    int t = threadIdx.x;
    #pragma unroll
    for (int i = 0; i < 16; i++) {
        int idx = i*256 + t;
        int c = idx >> 6, pl = idx & 63;
        tile[c][pl] = x[c*NP + p0 + pl];
    }
    __syncthreads();
    #pragma unroll
    for (int i = 0; i < 16; i++) {
        int idx = i*256 + t;
        int pl = idx >> 6, c = idx & 63;
        g_x[(p0 + pl)*64 + c] = tile[c][pl];
    }
}

// ---------------- offset conv: 128px x 32oc(18 used) x 576K -----------------
// SMEM: A hi/lo 32KB @0, B hi/lo 16KB @32768  -> 48KB
#define OFF_SMEM 49152

__global__ void __launch_bounds__(256, 2) offconv_kernel(int layer, const float* __restrict__ bias) {
    extern __shared__ char sm[];
    const uint32_t sA = smem_u32(sm);
    const uint32_t sB = sA + 32768;
    const float* __restrict__ in = layer ? g_h1 : g_x;
    const __nv_bfloat16* __restrict__ wsrc = &g_wob[layer][0][0][0];
    const int t = threadIdx.x;
    const int wid = t >> 5, lid = t & 31;
    const int mwarp = wid & 3, nwarp = wid >> 2;
    const int by = blockIdx.x >> 2;
    const int x0 = (blockIdx.x & 3) * 128;
    const int p0 = by*WW + x0;
    const int spx = t & 127;
    const int c0 = (t >> 7) * 32;

    float acc[2][2][4] = {};
    for (int k = 0; k < 9; k++) {
        if (k) __syncthreads();
        // stage B (16KB)
        {
            const uint4* src = (const uint4*)(wsrc + (size_t)k * 8192);
            uint4* dst = (uint4*)(sm + 32768);
            #pragma unroll
            for (int i = 0; i < 4; i++) dst[i*256 + t] = src[i*256 + t];
        }
        // build A: shifted copy, zero-pad borders
        {
            int yy = by + k/3 - 1, xx = x0 + spx + k%3 - 1;
            float sv[32];
            if (yy >= 0 && yy < HH && xx >= 0 && xx < WW) {
                const float4* sp = (const float4*)(in + ((size_t)(yy*WW + xx))*64 + c0);
                #pragma unroll
                for (int j = 0; j < 8; j++) {
                    float4 v = sp[j];
                    sv[4*j+0] = v.x; sv[4*j+1] = v.y; sv[4*j+2] = v.z; sv[4*j+3] = v.w;
                }
            } else {
                #pragma unroll
                for (int j = 0; j < 32; j++) sv[j] = 0.f;
            }
            #pragma unroll
            for (int j = 0; j < 4; j++) {
                uint4 hi, lo;
                split8(&sv[8*j], hi, lo);
                uint32_t off = SWZ((uint32_t)(spx*128 + (c0 + 8*j)*2));
                *(uint4*)(sm + off) = hi;
                *(uint4*)(sm + 16384 + off) = lo;
            }
        }
        __syncthreads();
        gemm_tap<2>(sA, sB, lid, mwarp, nwarp, acc);
    }
    // epilogue: write cols < 18
    #pragma unroll
    for (int mb = 0; mb < 2; mb++) {
        int row = mwarp*32 + mb*16 + (lid >> 2);
        #pragma unroll
        for (int nb = 0; nb < 2; nb++) {
            int colb = nwarp*16 + nb*8 + (lid & 3)*2;
            if (colb < 18) {
                float b0 = bias[colb], b1v = bias[colb+1];
                float* o0 = g_off + (size_t)(p0 + row)*18 + colb;
                float* o1 = g_off + (size_t)(p0 + row + 8)*18 + colb;
                o0[0] = acc[mb][nb][0] + b0;  o0[1] = acc[mb][nb][1] + b1v;
                o1[0] = acc[mb][nb][2] + b0;  o1[1] = acc[mb][nb][3] + b1v;
            }
        }
    }
}

// ---------------- deformable conv + BN + ReLU (+fused 1x1) ------------------
// SMEM: A hi/lo 32KB @0, B hi/lo 16KB @32768, offs 9216B @49152 -> 58368
#define DCN_SMEM 58368

template<int FUSE>
__global__ void __launch_bounds__(256, 2) dcn_kernel(int layer,
    const float* __restrict__ w1x1, const float* __restrict__ b1x1,
    float* __restrict__ out_f)
{
    extern __shared__ char sm[];
    const uint32_t sA = smem_u32(sm);
    const uint32_t sB = sA + 32768;
    float* offs = (float*)(sm + 49152);
    const float* __restrict__ in = layer ? g_h1 : g_x;
    const __nv_bfloat16* __restrict__ wsrc = &g_wdb[layer][0][0][0];
    const float* __restrict__ scl = g_bnscale[layer];
    const float* __restrict__ shf = g_bnshift[layer];
    const int t = threadIdx.x;
    const int wid = t >> 5, lid = t & 31;
    const int mwarp = wid & 3, nwarp = wid >> 2;
    const int by = blockIdx.x >> 2;
    const int x0 = (blockIdx.x & 3) * 128;
    const int p0 = by*WW + x0;
    const int spx = t & 127;
    const int c0 = (t >> 7) * 32;

    for (int i = t; i < 2304; i += 256) offs[i] = g_off[(size_t)p0*18 + i];

    float acc[2][4][4] = {};
    for (int k = 0; k < 9; k++) {
        __syncthreads();   // offs ready (k=0) / prior GEMM reads done (k>0)
        // stage B (16KB)
        {
            const uint4* src = (const uint4*)(wsrc + (size_t)k * 8192);
            uint4* dst = (uint4*)(sm + 32768);
            #pragma unroll
            for (int i = 0; i < 4; i++) dst[i*256 + t] = src[i*256 + t];
        }
        // build A: bilinear sample
        {
            float dy = offs[spx*18 + 2*k];
            float dx = offs[spx*18 + 2*k + 1];
            float py  = (float)(by + k/3 - 1) + dy;
            float pxf = (float)(x0 + spx + k%3 - 1) + dx;
            float fy = floorf(py), fx = floorf(pxf);
            float wy = py - fy, wx = pxf - fx;
            int yi = (int)fy, xi = (int)fx;
            float w00 = (1.f - wy)*(1.f - wx);
            float w01 = (1.f - wy)*wx;
            float w10 = wy*(1.f - wx);
            float w11 = wy*wx;
            bool vy0 = (yi   >= 0) && (yi   < HH);
            bool vy1 = (yi+1 >= 0) && (yi+1 < HH);
            bool vx0 = (xi   >= 0) && (xi   < WW);
            bool vx1 = (xi+1 >= 0) && (xi+1 < WW);
            float sv[32];
            #pragma unroll
            for (int j = 0; j < 32; j++) sv[j] = 0.f;
            #pragma unroll
            for (int ch = 0; ch < 2; ch++) {
                int cb = c0 + ch*16;
                float* svp = sv + ch*16;
                if (vy0 && vx0) corner_fma16(svp, in + ((size_t)( yi   *WW + xi  ))*64 + cb, w00);
                if (vy0 && vx1) corner_fma16(svp, in + ((size_t)( yi   *WW + xi+1))*64 + cb, w01);
                if (vy1 && vx0) corner_fma16(svp, in + ((size_t)((yi+1)*WW + xi  ))*64 + cb, w10);
                if (vy1 && vx1) corner_fma16(svp, in + ((size_t)((yi+1)*WW + xi+1))*64 + cb, w11);
            }
            #pragma unroll
            for (int j = 0; j < 4; j++) {
                uint4 hi, lo;
                split8(&sv[8*j], hi, lo);
                uint32_t off = SWZ((uint32_t)(spx*128 + (c0 + 8*j)*2));
                *(uint4*)(sm + off) = hi;
                *(uint4*)(sm + 16384 + off) = lo;
            }
        }
        __syncthreads();
        gemm_tap<4>(sA, sB, lid, mwarp, nwarp, acc);
    }

    if (!FUSE) {
        #pragma unroll
        for (int mb = 0; mb < 2; mb++) {
            int row = mwarp*32 + mb*16 + (lid >> 2);
            #pragma unroll
            for (int nb = 0; nb < 4; nb++) {
                int colb = nwarp*32 + nb*8 + (lid & 3)*2;
                float s0 = scl[colb], s1 = scl[colb+1];
                float h0 = shf[colb], h1v = shf[colb+1];
                float v00 = fmaxf(acc[mb][nb][0]*s0 + h0, 0.f);
                float v01 = fmaxf(acc[mb][nb][1]*s1 + h1v, 0.f);
                float v10 = fmaxf(acc[mb][nb][2]*s0 + h0, 0.f);
                float v11 = fmaxf(acc[mb][nb][3]*s1 + h1v, 0.f);
                *(float2*)(g_h1 + (size_t)(p0 + row)*64 + colb)     = make_float2(v00, v01);
                *(float2*)(g_h1 + (size_t)(p0 + row + 8)*64 + colb) = make_float2(v10, v11);
            }
        }
    } else {
        float pa[2] = {0.f, 0.f}, pb[2] = {0.f, 0.f};
        #pragma unroll
        for (int mb = 0; mb < 2; mb++) {
            #pragma unroll
            for (int nb = 0; nb < 4; nb++) {
                int colb = nwarp*32 + nb*8 + (lid & 3)*2;
                float s0 = scl[colb], s1 = scl[colb+1];
                float h0 = shf[colb], h1v = shf[colb+1];
                float w0 = w1x1[colb], w1 = w1x1[colb+1];
                float v00 = fmaxf(acc[mb][nb][0]*s0 + h0, 0.f);
                float v01 = fmaxf(acc[mb][nb][1]*s1 + h1v, 0.f);
                float v10 = fmaxf(acc[mb][nb][2]*s0 + h0, 0.f);
                float v11 = fmaxf(acc[mb][nb][3]*s1 + h1v, 0.f);
                pa[mb] += v00*w0 + v01*w1;
                pb[mb] += v10*w0 + v11*w1;
            }
            pa[mb] += __shfl_xor_sync(0xffffffffu, pa[mb], 1);
            pa[mb] += __shfl_xor_sync(0xffffffffu, pa[mb], 2);
            pb[mb] += __shfl_xor_sync(0xffffffffu, pb[mb], 1);
            pb[mb] += __shfl_xor_sync(0xffffffffu, pb[mb], 2);
        }
        float* red = (float*)(sm + 49152);
        __syncthreads();   // protect offs reuse (offs reads are long done; still need all warps here)
        if ((lid & 3) == 0) {
            #pragma unroll
            for (int mb = 0; mb < 2; mb++) {
                int row = mwarp*32 + mb*16 + (lid >> 2);
                red[nwarp*128 + row]     = pa[mb];
                red[nwarp*128 + row + 8] = pb[mb];
            }
        }
        __syncthreads();
        if (t < 128) out_f[p0 + t] = red[t] + red[128 + t] + b1x1[0];
    }
}

// ---------------- launch -----------------------------------------------------
extern "C" void kernel_launch(void* const* d_in, const int* in_sizes, int n_in,
                              void* d_out, int out_size) {
    const float* x    = (const float*)d_in[0];
    const float* w1o  = (const float*)d_in[1];
    const float* b1o  = (const float*)d_in[2];
    const float* wd1  = (const float*)d_in[3];
    const float* db1  = (const float*)d_in[4];
    const float* g1   = (const float*)d_in[5];
    const float* be1  = (const float*)d_in[6];
    const float* m1   = (const float*)d_in[7];
    const float* v1   = (const float*)d_in[8];
    const float* w2o  = (const float*)d_in[9];
    const float* b2o  = (const float*)d_in[10];
    const float* wd2  = (const float*)d_in[11];
    const float* db2  = (const float*)d_in[12];
    const float* g2   = (const float*)d_in[13];
    const float* be2  = (const float*)d_in[14];
    const float* m2   = (const float*)d_in[15];
    const float* v2   = (const float*)d_in[16];
    const float* wc   = (const float*)d_in[17];
    const float* bc   = (const float*)d_in[18];
    float* out = (float*)d_out;

    cudaFuncSetAttribute(offconv_kernel, cudaFuncAttributeMaxDynamicSharedMemorySize, OFF_SMEM);
    cudaFuncSetAttribute(dcn_kernel<0>,  cudaFuncAttributeMaxDynamicSharedMemorySize, DCN_SMEM);
    cudaFuncSetAttribute(dcn_kernel<1>,  cudaFuncAttributeMaxDynamicSharedMemorySize, DCN_SMEM);

    prep_kernel<<<64, 256>>>(w1o, w2o, wd1, wd2, db1, db2,
                             g1, be1, m1, v1, g2, be2, m2, v2);
    transpose_kernel<<<NP/64, 256>>>(x);
    offconv_kernel<<<2048, 256, OFF_SMEM>>>(0, b1o);
    dcn_kernel<0><<<2048, 256, DCN_SMEM>>>(0, nullptr, nullptr, nullptr);
    offconv_kernel<<<2048, 256, OFF_SMEM>>>(1, b2o);
    dcn_kernel<1><<<2048, 256, DCN_SMEM>>>(1, wc, bc, out);
}

// round 4
// speedup vs baseline: 2.5124x; 1.8194x over previous
#include <cuda_runtime.h>
#include <cuda_bf16.h>
#include <math.h>
#include <stdint.h>

#define HH 512
#define WW 512
#define NP (HH*WW)

// ---------------- scratch (device globals) ---------------------------------
__device__ float g_x[NP*64];                                  // input NHWC f32
__device__ float g_h1[NP*64];                                 // layer-1 out NHWC f32
__device__ float g_off[NP*18];                                // offsets [px][18]
__device__ __align__(16) __nv_bfloat16 g_wdb[2][9][2][64*64]; // dcn W: [layer][tap][hi/lo][SWZ(c*128+oc*2)]
__device__ __align__(16) __nv_bfloat16 g_wob[2][9][2][64*64]; // off W padded to 64 oc
__device__ float g_bnscale[2][64];
__device__ float g_bnshift[2][64];

// ---------------- helpers ----------------------------------------------------
__device__ __forceinline__ uint32_t smem_u32(const void* p) {
    uint32_t a;
    asm("{ .reg .u64 t; cvta.to.shared.u64 t, %1; cvt.u32.u64 %0, t; }" : "=r"(a) : "l"(p));
    return a;
}
#define SWZ(b) ((b) ^ (((b) >> 3) & 0x70))

#define LDSM4(r, addr) \
    asm volatile("ldmatrix.sync.aligned.m8n8.x4.shared.b16 {%0,%1,%2,%3}, [%4];" \
        : "=r"((r)[0]), "=r"((r)[1]), "=r"((r)[2]), "=r"((r)[3]) : "r"(addr))
#define LDSM4T(r, addr) \
    asm volatile("ldmatrix.sync.aligned.m8n8.x4.trans.shared.b16 {%0,%1,%2,%3}, [%4];" \
        : "=r"((r)[0]), "=r"((r)[1]), "=r"((r)[2]), "=r"((r)[3]) : "r"(addr))
#define MMA(d, a, b0_, b1_) \
    asm volatile("mma.sync.aligned.m16n8k16.row.col.f32.bf16.bf16.f32 " \
        "{%0,%1,%2,%3}, {%4,%5,%6,%7}, {%8,%9}, {%0,%1,%2,%3};" \
        : "+f"((d)[0]), "+f"((d)[1]), "+f"((d)[2]), "+f"((d)[3]) \
        : "r"((a)[0]), "r"((a)[1]), "r"((a)[2]), "r"((a)[3]), "r"(b0_), "r"(b1_))

// bf16 hi/lo split of 4 f32 -> two uint2 (packed bf16x2)
__device__ __forceinline__ void split4(const float* v, uint2& hi, uint2& lo) {
    uint32_t h[2], l[2];
    #pragma unroll
    for (int i = 0; i < 2; i++) {
        float a = v[2*i], b = v[2*i+1];
        __nv_bfloat16 ha = __float2bfloat16(a);
        __nv_bfloat16 hb = __float2bfloat16(b);
        __nv_bfloat16 la = __float2bfloat16(a - __bfloat162float(ha));
        __nv_bfloat16 lb = __float2bfloat16(b - __bfloat162float(hb));
        h[i] = ((uint32_t)__bfloat16_as_ushort(hb) << 16) | (uint32_t)__bfloat16_as_ushort(ha);
        l[i] = ((uint32_t)__bfloat16_as_ushort(lb) << 16) | (uint32_t)__bfloat16_as_ushort(la);
    }
    hi = make_uint2(h[0], h[1]);
    lo = make_uint2(l[0], l[1]);
}

// ---------------- shared GEMM: one tap, 3-pass bf16 split -------------------
// A: [128px][64c] bf16, 128B rows, SW128; hi at sA, lo at sA+16384.
// B: [64c][64oc] bf16, 128B rows, SW128; hi at sB, lo at sB+8192.
// Warp (mwarp 0..3, nwarp 0..1) computes 32px x (NB*8)oc.
template<int NB>
__device__ __forceinline__ void gemm_tap(uint32_t sA, uint32_t sB, int lid,
                                         int mwarp, int nwarp, float acc[2][NB][4]) {
    #pragma unroll
    for (int kb = 0; kb < 4; kb++) {
        uint32_t ah[2][4], al[2][4];
        #pragma unroll
        for (int mb = 0; mb < 2; mb++) {
            int row = mwarp*32 + mb*16 + (lid & 15);
            uint32_t a = sA + SWZ((uint32_t)(row*128 + (kb*16 + (lid>>4)*8)*2));
            LDSM4(ah[mb], a);
            LDSM4(al[mb], a + 16384);
        }
        #pragma unroll
        for (int nb2 = 0; nb2 < NB/2; nb2++) {
            int k = kb*16 + (lid & 15);
            int n = nwarp*(NB*8) + nb2*16 + (lid>>4)*8;
            uint32_t b = sB + SWZ((uint32_t)(k*128 + n*2));
            uint32_t bh[4], bl[4];
            LDSM4T(bh, b);
            LDSM4T(bl, b + 8192);
            #pragma unroll
            for (int mb = 0; mb < 2; mb++) {
                MMA(acc[mb][2*nb2],   ah[mb], bh[0], bh[1]);
                MMA(acc[mb][2*nb2],   al[mb], bh[0], bh[1]);
                MMA(acc[mb][2*nb2],   ah[mb], bl[0], bl[1]);
                MMA(acc[mb][2*nb2+1], ah[mb], bh[2], bh[3]);
                MMA(acc[mb][2*nb2+1], al[mb], bh[2], bh[3]);
                MMA(acc[mb][2*nb2+1], ah[mb], bl[2], bl[3]);
            }
        }
    }
}

// ---------------- prep: weight split/swizzle + BN folding -------------------
__global__ void prep_kernel(
    const float* __restrict__ w1o, const float* __restrict__ w2o,
    const float* __restrict__ wd1, const float* __restrict__ wd2,
    const float* __restrict__ db1, const float* __restrict__ db2,
    const float* __restrict__ g1, const float* __restrict__ b1,
    const float* __restrict__ m1, const float* __restrict__ v1,
    const float* __restrict__ g2, const float* __restrict__ b2,
    const float* __restrict__ m2, const float* __restrict__ v2)
{
    int idx = blockIdx.x * blockDim.x + threadIdx.x;
    int nth = gridDim.x * blockDim.x;
    for (int i = idx; i < 2*9*64*64; i += nth) {
        int layer = i / 36864, r = i % 36864;
        int k = r / 4096, rr = r & 4095;
        int c = rr >> 6, oc = rr & 63;
        uint32_t sidx = SWZ((uint32_t)(c*128 + oc*2)) >> 1;
        {
            float val = (layer ? wd2 : wd1)[(oc*64 + c)*9 + k];
            __nv_bfloat16 hi = __float2bfloat16(val);
            __nv_bfloat16 lo = __float2bfloat16(val - __bfloat162float(hi));
            g_wdb[layer][k][0][sidx] = hi;
            g_wdb[layer][k][1][sidx] = lo;
        }
        {
            float val = (oc < 18) ? (layer ? w2o : w1o)[(oc*64 + c)*9 + k] : 0.f;
            __nv_bfloat16 hi = __float2bfloat16(val);
            __nv_bfloat16 lo = __float2bfloat16(val - __bfloat162float(hi));
            g_wob[layer][k][0][sidx] = hi;
            g_wob[layer][k][1][sidx] = lo;
        }
    }
    if (idx < 64) {
        float s = g1[idx] * rsqrtf(v1[idx] + 1e-5f);
        g_bnscale[0][idx] = s;
        g_bnshift[0][idx] = b1[idx] - m1[idx]*s + db1[idx]*s;
        float s2 = g2[idx] * rsqrtf(v2[idx] + 1e-5f);
        g_bnscale[1][idx] = s2;
        g_bnshift[1][idx] = b2[idx] - m2[idx]*s2 + db2[idx]*s2;
    }
}

// ---------------- NCHW -> NHWC ----------------------------------------------
__global__ void __launch_bounds__(256) transpose_kernel(const float* __restrict__ x) {
    __shared__ float tile[64][65];
    int p0 = blockIdx.x * 64;
    int t = threadIdx.x;
    #pragma unroll
    for (int i = 0; i < 16; i++) {
        int idx = i*256 + t;
        int c = idx >> 6, pl = idx & 63;
        tile[c][pl] = x[c*NP + p0 + pl];
    }
    __syncthreads();
    #pragma unroll
    for (int i = 0; i < 16; i++) {
        int idx = i*256 + t;
        int pl = idx >> 6, c = idx & 63;
        g_x[(p0 + pl)*64 + c] = tile[c][pl];
    }
}

// ---------------- offset conv: 128px x 32oc(18 used) x 576K -----------------
// SMEM: A hi/lo 32KB @0, B hi/lo 16KB @32768  -> 48KB
#define OFF_SMEM 49152

__global__ void __launch_bounds__(256, 2) offconv_kernel(int layer, const float* __restrict__ bias) {
    extern __shared__ char sm[];
    const uint32_t sA = smem_u32(sm);
    const uint32_t sB = sA + 32768;
    const float* __restrict__ in = layer ? g_h1 : g_x;
    const __nv_bfloat16* __restrict__ wsrc = &g_wob[layer][0][0][0];
    const int t = threadIdx.x;
    const int wid = t >> 5, lid = t & 31;
    const int mwarp = wid & 3, nwarp = wid >> 2;
    const int by = blockIdx.x >> 2;
    const int x0 = (blockIdx.x & 3) * 128;
    const int p0 = by*WW + x0;
    const int ch4 = lid & 15;          // 4-channel group within pixel
    const int pxh = lid >> 4;          // 0/1: pixel within warp pair

    float acc[2][2][4] = {};
    for (int k = 0; k < 9; k++) {
        if (k) __syncthreads();
        // stage B (16KB)
        {
            const uint4* src = (const uint4*)(wsrc + (size_t)k * 8192);
            uint4* dst = (uint4*)(sm + 32768);
            #pragma unroll
            for (int i = 0; i < 4; i++) dst[i*256 + t] = src[i*256 + t];
        }
        // build A: shifted copy, lanes over channels (coalesced 256B/pixel)
        {
            int ky = k/3 - 1, kx = k%3 - 1;
            int yy = by + ky;
            #pragma unroll
            for (int it = 0; it < 8; it++) {
                int px = it*16 + wid*2 + pxh;
                int xx = x0 + px + kx;
                float sv[4] = {0.f, 0.f, 0.f, 0.f};
                if (yy >= 0 && yy < HH && xx >= 0 && xx < WW) {
                    float4 v = *(const float4*)(in + ((size_t)(yy*WW + xx))*64 + ch4*4);
                    sv[0] = v.x; sv[1] = v.y; sv[2] = v.z; sv[3] = v.w;
                }
                uint2 hi, lo;
                split4(sv, hi, lo);
                uint32_t off = SWZ((uint32_t)(px*128 + ch4*8));
                *(uint2*)(sm + off) = hi;
                *(uint2*)(sm + 16384 + off) = lo;
            }
        }
        __syncthreads();
        gemm_tap<2>(sA, sB, lid, mwarp, nwarp, acc);
    }
    // epilogue: write cols < 18
    #pragma unroll
    for (int mb = 0; mb < 2; mb++) {
        int row = mwarp*32 + mb*16 + (lid >> 2);
        #pragma unroll
        for (int nb = 0; nb < 2; nb++) {
            int colb = nwarp*16 + nb*8 + (lid & 3)*2;
            if (colb < 18) {
                float b0 = bias[colb], b1v = bias[colb+1];
                float* o0 = g_off + (size_t)(p0 + row)*18 + colb;
                float* o1 = g_off + (size_t)(p0 + row + 8)*18 + colb;
                o0[0] = acc[mb][nb][0] + b0;  o0[1] = acc[mb][nb][1] + b1v;
                o1[0] = acc[mb][nb][2] + b0;  o1[1] = acc[mb][nb][3] + b1v;
            }
        }
    }
}

// ---------------- deformable conv + BN + ReLU (+fused 1x1) ------------------
// SMEM: A hi/lo 32KB @0, B hi/lo 16KB @32768, offs 9216B @49152 -> 58368
#define DCN_SMEM 58368

template<int FUSE>
__global__ void __launch_bounds__(256, 2) dcn_kernel(int layer,
    const float* __restrict__ w1x1, const float* __restrict__ b1x1,
    float* __restrict__ out_f)
{
    extern __shared__ char sm[];
    const uint32_t sA = smem_u32(sm);
    const uint32_t sB = sA + 32768;
    float* offs = (float*)(sm + 49152);
    const float* __restrict__ in = layer ? g_h1 : g_x;
    const __nv_bfloat16* __restrict__ wsrc = &g_wdb[layer][0][0][0];
    const float* __restrict__ scl = g_bnscale[layer];
    const float* __restrict__ shf = g_bnshift[layer];
    const int t = threadIdx.x;
    const int wid = t >> 5, lid = t & 31;
    const int mwarp = wid & 3, nwarp = wid >> 2;
    const int by = blockIdx.x >> 2;
    const int x0 = (blockIdx.x & 3) * 128;
    const int p0 = by*WW + x0;
    const int ch4 = lid & 15;
    const int pxh = lid >> 4;

    for (int i = t; i < 2304; i += 256) offs[i] = g_off[(size_t)p0*18 + i];

    float acc[2][4][4] = {};
    for (int k = 0; k < 9; k++) {
        __syncthreads();   // offs ready (k=0) / prior GEMM reads done (k>0)
        // stage B (16KB)
        {
            const uint4* src = (const uint4*)(wsrc + (size_t)k * 8192);
            uint4* dst = (uint4*)(sm + 32768);
            #pragma unroll
            for (int i = 0; i < 4; i++) dst[i*256 + t] = src[i*256 + t];
        }
        // build A: bilinear sample, lanes over channels (coalesced)
        {
            int ky = k/3 - 1, kx = k%3 - 1;
            #pragma unroll
            for (int it = 0; it < 8; it++) {
                int px = it*16 + wid*2 + pxh;
                float dy = offs[px*18 + 2*k];
                float dx = offs[px*18 + 2*k + 1];
                float py  = (float)(by + ky) + dy;
                float pxf = (float)(x0 + px + kx) + dx;
                float fy = floorf(py), fx = floorf(pxf);
                float wy = py - fy, wx = pxf - fx;
                int yi = (int)fy, xi = (int)fx;
                float w00 = (1.f - wy)*(1.f - wx);
                float w01 = (1.f - wy)*wx;
                float w10 = wy*(1.f - wx);
                float w11 = wy*wx;
                bool vy0 = (yi   >= 0) && (yi   < HH);
                bool vy1 = (yi+1 >= 0) && (yi+1 < HH);
                bool vx0 = (xi   >= 0) && (xi   < WW);
                bool vx1 = (xi+1 >= 0) && (xi+1 < WW);
                const float* base = in + ((size_t)(yi*WW + xi))*64 + ch4*4;
                float sv[4] = {0.f, 0.f, 0.f, 0.f};
                if (vy0 && vx0) {
                    float4 v = *(const float4*)base;
                    sv[0] += w00*v.x; sv[1] += w00*v.y; sv[2] += w00*v.z; sv[3] += w00*v.w;
                }
                if (vy0 && vx1) {
                    float4 v = *(const float4*)(base + 64);
                    sv[0] += w01*v.x; sv[1] += w01*v.y; sv[2] += w01*v.z; sv[3] += w01*v.w;
                }
                if (vy1 && vx0) {
                    float4 v = *(const float4*)(base + (size_t)WW*64);
                    sv[0] += w10*v.x; sv[1] += w10*v.y; sv[2] += w10*v.z; sv[3] += w10*v.w;
                }
                if (vy1 && vx1) {
                    float4 v = *(const float4*)(base + (size_t)WW*64 + 64);
                    sv[0] += w11*v.x; sv[1] += w11*v.y; sv[2] += w11*v.z; sv[3] += w11*v.w;
                }
                uint2 hi, lo;
                split4(sv, hi, lo);
                uint32_t off = SWZ((uint32_t)(px*128 + ch4*8));
                *(uint2*)(sm + off) = hi;
                *(uint2*)(sm + 16384 + off) = lo;
            }
        }
        __syncthreads();
        gemm_tap<4>(sA, sB, lid, mwarp, nwarp, acc);
    }

    if (!FUSE) {
        #pragma unroll
        for (int mb = 0; mb < 2; mb++) {
            int row = mwarp*32 + mb*16 + (lid >> 2);
            #pragma unroll
            for (int nb = 0; nb < 4; nb++) {
                int colb = nwarp*32 + nb*8 + (lid & 3)*2;
                float s0 = scl[colb], s1 = scl[colb+1];
                float h0 = shf[colb], h1v = shf[colb+1];
                float v00 = fmaxf(acc[mb][nb][0]*s0 + h0, 0.f);
                float v01 = fmaxf(acc[mb][nb][1]*s1 + h1v, 0.f);
                float v10 = fmaxf(acc[mb][nb][2]*s0 + h0, 0.f);
                float v11 = fmaxf(acc[mb][nb][3]*s1 + h1v, 0.f);
                *(float2*)(g_h1 + (size_t)(p0 + row)*64 + colb)     = make_float2(v00, v01);
                *(float2*)(g_h1 + (size_t)(p0 + row + 8)*64 + colb) = make_float2(v10, v11);
            }
        }
    } else {
        float pa[2] = {0.f, 0.f}, pb[2] = {0.f, 0.f};
        #pragma unroll
        for (int mb = 0; mb < 2; mb++) {
            #pragma unroll
            for (int nb = 0; nb < 4; nb++) {
                int colb = nwarp*32 + nb*8 + (lid & 3)*2;
                float s0 = scl[colb], s1 = scl[colb+1];
                float h0 = shf[colb], h1v = shf[colb+1];
                float w0 = w1x1[colb], w1 = w1x1[colb+1];
                float v00 = fmaxf(acc[mb][nb][0]*s0 + h0, 0.f);
                float v01 = fmaxf(acc[mb][nb][1]*s1 + h1v, 0.f);
                float v10 = fmaxf(acc[mb][nb][2]*s0 + h0, 0.f);
                float v11 = fmaxf(acc[mb][nb][3]*s1 + h1v, 0.f);
                pa[mb] += v00*w0 + v01*w1;
                pb[mb] += v10*w0 + v11*w1;
            }
            pa[mb] += __shfl_xor_sync(0xffffffffu, pa[mb], 1);
            pa[mb] += __shfl_xor_sync(0xffffffffu, pa[mb], 2);
            pb[mb] += __shfl_xor_sync(0xffffffffu, pb[mb], 1);
            pb[mb] += __shfl_xor_sync(0xffffffffu, pb[mb], 2);
        }
        float* red = (float*)(sm + 49152);
        __syncthreads();
        if ((lid & 3) == 0) {
            #pragma unroll
            for (int mb = 0; mb < 2; mb++) {
                int row = mwarp*32 + mb*16 + (lid >> 2);
                red[nwarp*128 + row]     = pa[mb];
                red[nwarp*128 + row + 8] = pb[mb];
            }
        }
        __syncthreads();
        if (t < 128) out_f[p0 + t] = red[t] + red[128 + t] + b1x1[0];
    }
}

// ---------------- launch -----------------------------------------------------
extern "C" void kernel_launch(void* const* d_in, const int* in_sizes, int n_in,
                              void* d_out, int out_size) {
    const float* x    = (const float*)d_in[0];
    const float* w1o  = (const float*)d_in[1];
    const float* b1o  = (const float*)d_in[2];
    const float* wd1  = (const float*)d_in[3];
    const float* db1  = (const float*)d_in[4];
    const float* g1   = (const float*)d_in[5];
    const float* be1  = (const float*)d_in[6];
    const float* m1   = (const float*)d_in[7];
    const float* v1   = (const float*)d_in[8];
    const float* w2o  = (const float*)d_in[9];
    const float* b2o  = (const float*)d_in[10];
    const float* wd2  = (const float*)d_in[11];
    const float* db2  = (const float*)d_in[12];
    const float* g2   = (const float*)d_in[13];
    const float* be2  = (const float*)d_in[14];
    const float* m2   = (const float*)d_in[15];
    const float* v2   = (const float*)d_in[16];
    const float* wc   = (const float*)d_in[17];
    const float* bc   = (const float*)d_in[18];
    float* out = (float*)d_out;

    cudaFuncSetAttribute(offconv_kernel, cudaFuncAttributeMaxDynamicSharedMemorySize, OFF_SMEM);
    cudaFuncSetAttribute(dcn_kernel<0>,  cudaFuncAttributeMaxDynamicSharedMemorySize, DCN_SMEM);
    cudaFuncSetAttribute(dcn_kernel<1>,  cudaFuncAttributeMaxDynamicSharedMemorySize, DCN_SMEM);

    prep_kernel<<<64, 256>>>(w1o, w2o, wd1, wd2, db1, db2,
                             g1, be1, m1, v1, g2, be2, m2, v2);
    transpose_kernel<<<NP/64, 256>>>(x);
    offconv_kernel<<<2048, 256, OFF_SMEM>>>(0, b1o);
    dcn_kernel<0><<<2048, 256, DCN_SMEM>>>(0, nullptr, nullptr, nullptr);
    offconv_kernel<<<2048, 256, OFF_SMEM>>>(1, b2o);
    dcn_kernel<1><<<2048, 256, DCN_SMEM>>>(1, wc, bc, out);
}

// round 5
// speedup vs baseline: 2.6225x; 1.0438x over previous
#include <cuda_runtime.h>
#include <cuda_bf16.h>
#include <math.h>
#include <stdint.h>

#define HH 512
#define WW 512
#define NP (HH*WW)

// ---------------- scratch (device globals) ---------------------------------
__device__ float g_x[NP*64];                                  // input NHWC f32
__device__ float g_h1[NP*64];                                 // layer-1 out NHWC f32
__device__ float g_off[NP*18];                                // offsets [px][18]
__device__ __align__(16) __nv_bfloat16 g_wdb[2][9][2][64*64]; // dcn W: [layer][tap][hi/lo][SWZ(c*128+oc*2)]
__device__ __align__(16) __nv_bfloat16 g_wob[2][9][2][64*64]; // off W padded to 64 oc
__device__ float g_bnscale[2][64];
__device__ float g_bnshift[2][64];

// ---------------- helpers ----------------------------------------------------
__device__ __forceinline__ uint32_t smem_u32(const void* p) {
    uint32_t a;
    asm("{ .reg .u64 t; cvta.to.shared.u64 t, %1; cvt.u32.u64 %0, t; }" : "=r"(a) : "l"(p));
    return a;
}
#define SWZ(b) ((b) ^ (((b) >> 3) & 0x70))

#define CP_ASYNC16(dst, src) \
    asm volatile("cp.async.cg.shared.global [%0], [%1], 16;" :: "r"(dst), "l"(src))
#define CP_COMMIT()  asm volatile("cp.async.commit_group;")
#define CP_WAIT0()   asm volatile("cp.async.wait_group 0;")

#define LDSM4(r, addr) \
    asm volatile("ldmatrix.sync.aligned.m8n8.x4.shared.b16 {%0,%1,%2,%3}, [%4];" \
        : "=r"((r)[0]), "=r"((r)[1]), "=r"((r)[2]), "=r"((r)[3]) : "r"(addr))
#define LDSM4T(r, addr) \
    asm volatile("ldmatrix.sync.aligned.m8n8.x4.trans.shared.b16 {%0,%1,%2,%3}, [%4];" \
        : "=r"((r)[0]), "=r"((r)[1]), "=r"((r)[2]), "=r"((r)[3]) : "r"(addr))
#define MMA(d, a, b0_, b1_) \
    asm volatile("mma.sync.aligned.m16n8k16.row.col.f32.bf16.bf16.f32 " \
        "{%0,%1,%2,%3}, {%4,%5,%6,%7}, {%8,%9}, {%0,%1,%2,%3};" \
        : "+f"((d)[0]), "+f"((d)[1]), "+f"((d)[2]), "+f"((d)[3]) \
        : "r"((a)[0]), "r"((a)[1]), "r"((a)[2]), "r"((a)[3]), "r"(b0_), "r"(b1_))

// bf16 hi/lo split of 4 f32 -> two uint2 (packed bf16x2)
__device__ __forceinline__ void split4(const float* v, uint2& hi, uint2& lo) {
    uint32_t h[2], l[2];
    #pragma unroll
    for (int i = 0; i < 2; i++) {
        float a = v[2*i], b = v[2*i+1];
        __nv_bfloat16 ha = __float2bfloat16(a);
        __nv_bfloat16 hb = __float2bfloat16(b);
        __nv_bfloat16 la = __float2bfloat16(a - __bfloat162float(ha));
        __nv_bfloat16 lb = __float2bfloat16(b - __bfloat162float(hb));
        h[i] = ((uint32_t)__bfloat16_as_ushort(hb) << 16) | (uint32_t)__bfloat16_as_ushort(ha);
        l[i] = ((uint32_t)__bfloat16_as_ushort(lb) << 16) | (uint32_t)__bfloat16_as_ushort(la);
    }
    hi = make_uint2(h[0], h[1]);
    lo = make_uint2(l[0], l[1]);
}

// ---------------- shared GEMM: one tap, 3-pass bf16 split -------------------
// A: [128px][64c] bf16, 128B rows, SW128; hi at sAb, lo at sAb+16384.
// B: [64c][64oc] bf16, 128B rows, SW128; hi at sBb, lo at sBb+8192.
template<int NB>
__device__ __forceinline__ void gemm_tap(uint32_t sAb, uint32_t sBb, int lid,
                                         int mwarp, int nwarp, float acc[2][NB][4]) {
    #pragma unroll
    for (int kb = 0; kb < 4; kb++) {
        uint32_t ah[2][4], al[2][4];
        #pragma unroll
        for (int mb = 0; mb < 2; mb++) {
            int row = mwarp*32 + mb*16 + (lid & 15);
            uint32_t a = sAb + SWZ((uint32_t)(row*128 + (kb*16 + (lid>>4)*8)*2));
            LDSM4(ah[mb], a);
            LDSM4(al[mb], a + 16384);
        }
        #pragma unroll
        for (int nb2 = 0; nb2 < NB/2; nb2++) {
            int k = kb*16 + (lid & 15);
            int n = nwarp*(NB*8) + nb2*16 + (lid>>4)*8;
            uint32_t b = sBb + SWZ((uint32_t)(k*128 + n*2));
            uint32_t bh[4], bl[4];
            LDSM4T(bh, b);
            LDSM4T(bl, b + 8192);
            #pragma unroll
            for (int mb = 0; mb < 2; mb++) {
                MMA(acc[mb][2*nb2],   ah[mb], bh[0], bh[1]);
                MMA(acc[mb][2*nb2],   al[mb], bh[0], bh[1]);
                MMA(acc[mb][2*nb2],   ah[mb], bl[0], bl[1]);
                MMA(acc[mb][2*nb2+1], ah[mb], bh[2], bh[3]);
                MMA(acc[mb][2*nb2+1], al[mb], bh[2], bh[3]);
                MMA(acc[mb][2*nb2+1], ah[mb], bl[2], bl[3]);
            }
        }
    }
}

// stage one tap's weights (16KB) via cp.async
__device__ __forceinline__ void stage_b(const __nv_bfloat16* __restrict__ wsrc, int k,
                                        uint32_t sBb, int t) {
    const char* src = (const char*)(wsrc + (size_t)k * 8192);
    #pragma unroll
    for (int i = 0; i < 4; i++)
        CP_ASYNC16(sBb + (uint32_t)(i*256 + t)*16, src + (size_t)(i*256 + t)*16);
}

// branchless bilinear sample of one tap into A buffer (hi/lo)
__device__ __forceinline__ void sample_dcn(const float* __restrict__ in,
                                           const float* __restrict__ offs,
                                           int by, int x0, int k,
                                           char* sm, uint32_t abuf,
                                           int wid, int pxh, int ch4) {
    int ky = k/3 - 1, kx = k%3 - 1;
    #pragma unroll
    for (int it = 0; it < 8; it++) {
        int px = it*16 + wid*2 + pxh;
        float dy = offs[px*18 + 2*k];
        float dx = offs[px*18 + 2*k + 1];
        float py  = (float)(by + ky) + dy;
        float pxf = (float)(x0 + px + kx) + dx;
        float fy = floorf(py), fx = floorf(pxf);
        float wy = py - fy, wx = pxf - fx;
        int yi = (int)fy, xi = (int)fx;
        float fy0 = (yi   >= 0 && yi   < HH) ? 1.f : 0.f;
        float fy1 = (yi+1 >= 0 && yi+1 < HH) ? 1.f : 0.f;
        float fx0 = (xi   >= 0 && xi   < WW) ? 1.f : 0.f;
        float fx1 = (xi+1 >= 0 && xi+1 < WW) ? 1.f : 0.f;
        float w00 = (1.f - wy)*(1.f - wx) * fy0 * fx0;
        float w01 = (1.f - wy)*wx         * fy0 * fx1;
        float w10 = wy*(1.f - wx)         * fy1 * fx0;
        float w11 = wy*wx                 * fy1 * fx1;
        int y0c = min(max(yi,     0), HH-1);
        int y1c = min(max(yi + 1, 0), HH-1);
        int x0c = min(max(xi,     0), WW-1);
        int x1c = min(max(xi + 1, 0), WW-1);
        const float* r0 = in + ((size_t)(y0c*WW))*64 + ch4*4;
        const float* r1 = in + ((size_t)(y1c*WW))*64 + ch4*4;
        float4 v00 = *(const float4*)(r0 + (size_t)x0c*64);
        float4 v01 = *(const float4*)(r0 + (size_t)x1c*64);
        float4 v10 = *(const float4*)(r1 + (size_t)x0c*64);
        float4 v11 = *(const float4*)(r1 + (size_t)x1c*64);
        float sv[4];
        sv[0] = w00*v00.x + w01*v01.x + w10*v10.x + w11*v11.x;
        sv[1] = w00*v00.y + w01*v01.y + w10*v10.y + w11*v11.y;
        sv[2] = w00*v00.z + w01*v01.z + w10*v10.z + w11*v11.z;
        sv[3] = w00*v00.w + w01*v01.w + w10*v10.w + w11*v11.w;
        uint2 hi, lo;
        split4(sv, hi, lo);
        uint32_t off = SWZ((uint32_t)(px*128 + ch4*8));
        *(uint2*)(sm + abuf + off) = hi;
        *(uint2*)(sm + abuf + 16384 + off) = lo;
    }
}

// branchless shifted-copy sample (offset conv A build)
__device__ __forceinline__ void sample_off(const float* __restrict__ in,
                                           int by, int x0, int k,
                                           char* sm, uint32_t abuf,
                                           int wid, int pxh, int ch4) {
    int ky = k/3 - 1, kx = k%3 - 1;
    int yy = by + ky;
    float fv = (yy >= 0 && yy < HH) ? 1.f : 0.f;
    int yc = min(max(yy, 0), HH-1);
    const float* row = in + ((size_t)(yc*WW))*64 + ch4*4;
    #pragma unroll
    for (int it = 0; it < 8; it++) {
        int px = it*16 + wid*2 + pxh;
        int xx = x0 + px + kx;
        float f = fv * ((xx >= 0 && xx < WW) ? 1.f : 0.f);
        int xc = min(max(xx, 0), WW-1);
        float4 v = *(const float4*)(row + (size_t)xc*64);
        float sv[4] = {f*v.x, f*v.y, f*v.z, f*v.w};
        uint2 hi, lo;
        split4(sv, hi, lo);
        uint32_t off = SWZ((uint32_t)(px*128 + ch4*8));
        *(uint2*)(sm + abuf + off) = hi;
        *(uint2*)(sm + abuf + 16384 + off) = lo;
    }
}

// ---------------- prep: weight split/swizzle + BN folding -------------------
__global__ void prep_kernel(
    const float* __restrict__ w1o, const float* __restrict__ w2o,
    const float* __restrict__ wd1, const float* __restrict__ wd2,
    const float* __restrict__ db1, const float* __restrict__ db2,
    const float* __restrict__ g1, const float* __restrict__ b1,
    const float* __restrict__ m1, const float* __restrict__ v1,
    const float* __restrict__ g2, const float* __restrict__ b2,
    const float* __restrict__ m2, const float* __restrict__ v2)
{
    int idx = blockIdx.x * blockDim.x + threadIdx.x;
    int nth = gridDim.x * blockDim.x;
    for (int i = idx; i < 2*9*64*64; i += nth) {
        int layer = i / 36864, r = i % 36864;
        int k = r / 4096, rr = r & 4095;
        int c = rr >> 6, oc = rr & 63;
        uint32_t sidx = SWZ((uint32_t)(c*128 + oc*2)) >> 1;
        {
            float val = (layer ? wd2 : wd1)[(oc*64 + c)*9 + k];
            __nv_bfloat16 hi = __float2bfloat16(val);
            __nv_bfloat16 lo = __float2bfloat16(val - __bfloat162float(hi));
            g_wdb[layer][k][0][sidx] = hi;
            g_wdb[layer][k][1][sidx] = lo;
        }
        {
            float val = (oc < 18) ? (layer ? w2o : w1o)[(oc*64 + c)*9 + k] : 0.f;
            __nv_bfloat16 hi = __float2bfloat16(val);
            __nv_bfloat16 lo = __float2bfloat16(val - __bfloat162float(hi));
            g_wob[layer][k][0][sidx] = hi;
            g_wob[layer][k][1][sidx] = lo;
        }
    }
    if (idx < 64) {
        float s = g1[idx] * rsqrtf(v1[idx] + 1e-5f);
        g_bnscale[0][idx] = s;
        g_bnshift[0][idx] = b1[idx] - m1[idx]*s + db1[idx]*s;
        float s2 = g2[idx] * rsqrtf(v2[idx] + 1e-5f);
        g_bnscale[1][idx] = s2;
        g_bnshift[1][idx] = b2[idx] - m2[idx]*s2 + db2[idx]*s2;
    }
}

// ---------------- NCHW -> NHWC ----------------------------------------------
__global__ void __launch_bounds__(256) transpose_kernel(const float* __restrict__ x) {
    __shared__ float tile[64][65];
    int p0 = blockIdx.x * 64;
    int t = threadIdx.x;
    #pragma unroll
    for (int i = 0; i < 16; i++) {
        int idx = i*256 + t;
        int c = idx >> 6, pl = idx & 63;
        tile[c][pl] = x[c*NP + p0 + pl];
    }
    __syncthreads();
    #pragma unroll
    for (int i = 0; i < 16; i++) {
        int idx = i*256 + t;
        int pl = idx >> 6, c = idx & 63;
        g_x[(p0 + pl)*64 + c] = tile[c][pl];
    }
}

// ---------------- offset conv: pipelined, double-buffered -------------------
// SMEM: A0 hi/lo 32K @0, A1 hi/lo 32K @32768, B0 16K @65536, B1 16K @81920
#define OFF_SMEM 98304

__global__ void __launch_bounds__(256, 2) offconv_kernel(int layer, const float* __restrict__ bias) {
    extern __shared__ char sm[];
    const uint32_t sbase = smem_u32(sm);
    const float* __restrict__ in = layer ? g_h1 : g_x;
    const __nv_bfloat16* __restrict__ wsrc = &g_wob[layer][0][0][0];
    const int t = threadIdx.x;
    const int wid = t >> 5, lid = t & 31;
    const int mwarp = wid & 3, nwarp = wid >> 2;
    const int by = blockIdx.x >> 2;
    const int x0 = (blockIdx.x & 3) * 128;
    const int p0 = by*WW + x0;
    const int ch4 = lid & 15;
    const int pxh = lid >> 4;

    // prologue: buffers for tap 0
    stage_b(wsrc, 0, sbase + 65536, t);
    CP_COMMIT();
    sample_off(in, by, x0, 0, sm, 0, wid, pxh, ch4);
    CP_WAIT0();
    __syncthreads();

    float acc[2][2][4] = {};
    for (int k = 0; k < 9; k++) {
        uint32_t cab = (uint32_t)(k & 1) * 32768;
        uint32_t cbb = 65536u + (uint32_t)(k & 1) * 16384;
        if (k < 8) {
            uint32_t nab = (uint32_t)((k+1) & 1) * 32768;
            uint32_t nbb = 65536u + (uint32_t)((k+1) & 1) * 16384;
            stage_b(wsrc, k+1, sbase + nbb, t);
            CP_COMMIT();
            sample_off(in, by, x0, k+1, sm, nab, wid, pxh, ch4);
        }
        gemm_tap<2>(sbase + cab, sbase + cbb, lid, mwarp, nwarp, acc);
        CP_WAIT0();
        __syncthreads();
    }
    // epilogue: write cols < 18
    #pragma unroll
    for (int mb = 0; mb < 2; mb++) {
        int row = mwarp*32 + mb*16 + (lid >> 2);
        #pragma unroll
        for (int nb = 0; nb < 2; nb++) {
            int colb = nwarp*16 + nb*8 + (lid & 3)*2;
            if (colb < 18) {
                float b0 = bias[colb], b1v = bias[colb+1];
                float* o0 = g_off + (size_t)(p0 + row)*18 + colb;
                float* o1 = g_off + (size_t)(p0 + row + 8)*18 + colb;
                o0[0] = acc[mb][nb][0] + b0;  o0[1] = acc[mb][nb][1] + b1v;
                o1[0] = acc[mb][nb][2] + b0;  o1[1] = acc[mb][nb][3] + b1v;
            }
        }
    }
}

// ---------------- deformable conv: pipelined + BN + ReLU (+fused 1x1) -------
// SMEM: A0 32K @0, A1 32K @32768, B0 16K @65536, B1 16K @81920, offs @98304
#define DCN_SMEM 107520

template<int FUSE>
__global__ void __launch_bounds__(256, 2) dcn_kernel(int layer,
    const float* __restrict__ w1x1, const float* __restrict__ b1x1,
    float* __restrict__ out_f)
{
    extern __shared__ char sm[];
    const uint32_t sbase = smem_u32(sm);
    float* offs = (float*)(sm + 98304);
    const float* __restrict__ in = layer ? g_h1 : g_x;
    const __nv_bfloat16* __restrict__ wsrc = &g_wdb[layer][0][0][0];
    const float* __restrict__ scl = g_bnscale[layer];
    const float* __restrict__ shf = g_bnshift[layer];
    const int t = threadIdx.x;
    const int wid = t >> 5, lid = t & 31;
    const int mwarp = wid & 3, nwarp = wid >> 2;
    const int by = blockIdx.x >> 2;
    const int x0 = (blockIdx.x & 3) * 128;
    const int p0 = by*WW + x0;
    const int ch4 = lid & 15;
    const int pxh = lid >> 4;

    for (int i = t; i < 2304; i += 256) offs[i] = g_off[(size_t)p0*18 + i];
    __syncthreads();   // offs ready

    // prologue: buffers for tap 0
    stage_b(wsrc, 0, sbase + 65536, t);
    CP_COMMIT();
    sample_dcn(in, offs, by, x0, 0, sm, 0, wid, pxh, ch4);
    CP_WAIT0();
    __syncthreads();

    float acc[2][4][4] = {};
    for (int k = 0; k < 9; k++) {
        uint32_t cab = (uint32_t)(k & 1) * 32768;
        uint32_t cbb = 65536u + (uint32_t)(k & 1) * 16384;
        if (k < 8) {
            uint32_t nab = (uint32_t)((k+1) & 1) * 32768;
            uint32_t nbb = 65536u + (uint32_t)((k+1) & 1) * 16384;
            stage_b(wsrc, k+1, sbase + nbb, t);
            CP_COMMIT();
            sample_dcn(in, offs, by, x0, k+1, sm, nab, wid, pxh, ch4);
        }
        gemm_tap<4>(sbase + cab, sbase + cbb, lid, mwarp, nwarp, acc);
        CP_WAIT0();
        __syncthreads();
    }

    if (!FUSE) {
        #pragma unroll
        for (int mb = 0; mb < 2; mb++) {
            int row = mwarp*32 + mb*16 + (lid >> 2);
            #pragma unroll
            for (int nb = 0; nb < 4; nb++) {
                int colb = nwarp*32 + nb*8 + (lid & 3)*2;
                float s0 = scl[colb], s1 = scl[colb+1];
                float h0 = shf[colb], h1v = shf[colb+1];
                float v00 = fmaxf(acc[mb][nb][0]*s0 + h0, 0.f);
                float v01 = fmaxf(acc[mb][nb][1]*s1 + h1v, 0.f);
                float v10 = fmaxf(acc[mb][nb][2]*s0 + h0, 0.f);
                float v11 = fmaxf(acc[mb][nb][3]*s1 + h1v, 0.f);
                *(float2*)(g_h1 + (size_t)(p0 + row)*64 + colb)     = make_float2(v00, v01);
                *(float2*)(g_h1 + (size_t)(p0 + row + 8)*64 + colb) = make_float2(v10, v11);
            }
        }
    } else {
        float pa[2] = {0.f, 0.f}, pb[2] = {0.f, 0.f};
        #pragma unroll
        for (int mb = 0; mb < 2; mb++) {
            #pragma unroll
            for (int nb = 0; nb < 4; nb++) {
                int colb = nwarp*32 + nb*8 + (lid & 3)*2;
                float s0 = scl[colb], s1 = scl[colb+1];
                float h0 = shf[colb], h1v = shf[colb+1];
                float w0 = w1x1[colb], w1 = w1x1[colb+1];
                float v00 = fmaxf(acc[mb][nb][0]*s0 + h0, 0.f);
                float v01 = fmaxf(acc[mb][nb][1]*s1 + h1v, 0.f);
                float v10 = fmaxf(acc[mb][nb][2]*s0 + h0, 0.f);
                float v11 = fmaxf(acc[mb][nb][3]*s1 + h1v, 0.f);
                pa[mb] += v00*w0 + v01*w1;
                pb[mb] += v10*w0 + v11*w1;
            }
            pa[mb] += __shfl_xor_sync(0xffffffffu, pa[mb], 1);
            pa[mb] += __shfl_xor_sync(0xffffffffu, pa[mb], 2);
            pb[mb] += __shfl_xor_sync(0xffffffffu, pb[mb], 1);
            pb[mb] += __shfl_xor_sync(0xffffffffu, pb[mb], 2);
        }
        float* red = (float*)(sm + 98304);   // offs no longer needed
        if ((lid & 3) == 0) {
            #pragma unroll
            for (int mb = 0; mb < 2; mb++) {
                int row = mwarp*32 + mb*16 + (lid >> 2);
                red[nwarp*128 + row]     = pa[mb];
                red[nwarp*128 + row + 8] = pb[mb];
            }
        }
        __syncthreads();
        if (t < 128) out_f[p0 + t] = red[t] + red[128 + t] + b1x1[0];
    }
}

// ---------------- launch -----------------------------------------------------
extern "C" void kernel_launch(void* const* d_in, const int* in_sizes, int n_in,
                              void* d_out, int out_size) {
    const float* x    = (const float*)d_in[0];
    const float* w1o  = (const float*)d_in[1];
    const float* b1o  = (const float*)d_in[2];
    const float* wd1  = (const float*)d_in[3];
    const float* db1  = (const float*)d_in[4];
    const float* g1   = (const float*)d_in[5];
    const float* be1  = (const float*)d_in[6];
    const float* m1   = (const float*)d_in[7];
    const float* v1   = (const float*)d_in[8];
    const float* w2o  = (const float*)d_in[9];
    const float* b2o  = (const float*)d_in[10];
    const float* wd2  = (const float*)d_in[11];
    const float* db2  = (const float*)d_in[12];
    const float* g2   = (const float*)d_in[13];
    const float* be2  = (const float*)d_in[14];
    const float* m2   = (const float*)d_in[15];
    const float* v2   = (const float*)d_in[16];
    const float* wc   = (const float*)d_in[17];
    const float* bc   = (const float*)d_in[18];
    float* out = (float*)d_out;

    cudaFuncSetAttribute(offconv_kernel, cudaFuncAttributeMaxDynamicSharedMemorySize, OFF_SMEM);
    cudaFuncSetAttribute(dcn_kernel<0>,  cudaFuncAttributeMaxDynamicSharedMemorySize, DCN_SMEM);
    cudaFuncSetAttribute(dcn_kernel<1>,  cudaFuncAttributeMaxDynamicSharedMemorySize, DCN_SMEM);

    prep_kernel<<<64, 256>>>(w1o, w2o, wd1, wd2, db1, db2,
                             g1, be1, m1, v1, g2, be2, m2, v2);
    transpose_kernel<<<NP/64, 256>>>(x);
    offconv_kernel<<<2048, 256, OFF_SMEM>>>(0, b1o);
    dcn_kernel<0><<<2048, 256, DCN_SMEM>>>(0, nullptr, nullptr, nullptr);
    offconv_kernel<<<2048, 256, OFF_SMEM>>>(1, b2o);
    dcn_kernel<1><<<2048, 256, DCN_SMEM>>>(1, wc, bc, out);
}

// round 6
// speedup vs baseline: 3.6665x; 1.3981x over previous
#include <cuda_runtime.h>
#include <cuda_fp16.h>
#include <math.h>
#include <stdint.h>

#define HH 512
#define WW 512
#define NP (HH*WW)

// ---------------- scratch (device globals) ---------------------------------
__device__ float g_x[NP*64];                              // input NHWC f32
__device__ float g_h1[NP*64];                             // layer-1 out NHWC f32
__device__ float g_off[NP*18];                            // offsets [px][18]
__device__ __align__(16) __half g_wdb[2][9][2][64*64];    // dcn W: [layer][tap][hi/lo][SWZ(c*128+oc*2)]
__device__ __align__(16) __half g_wob[2][9][2][64*64];    // off W padded to 64 oc
__device__ float g_bnscale[2][64];
__device__ float g_bnshift[2][64];

// ---------------- helpers ----------------------------------------------------
__device__ __forceinline__ uint32_t smem_u32(const void* p) {
    uint32_t a;
    asm("{ .reg .u64 t; cvta.to.shared.u64 t, %1; cvt.u32.u64 %0, t; }" : "=r"(a) : "l"(p));
    return a;
}
#define SWZ(b) ((b) ^ (((b) >> 3) & 0x70))

#define CP_ASYNC16(dst, src) \
    asm volatile("cp.async.cg.shared.global [%0], [%1], 16;" :: "r"(dst), "l"(src))
#define CP_COMMIT()  asm volatile("cp.async.commit_group;")
#define CP_WAIT0()   asm volatile("cp.async.wait_group 0;")

#define LDSM4(r, addr) \
    asm volatile("ldmatrix.sync.aligned.m8n8.x4.shared.b16 {%0,%1,%2,%3}, [%4];" \
        : "=r"((r)[0]), "=r"((r)[1]), "=r"((r)[2]), "=r"((r)[3]) : "r"(addr))
#define LDSM4T(r, addr) \
    asm volatile("ldmatrix.sync.aligned.m8n8.x4.trans.shared.b16 {%0,%1,%2,%3}, [%4];" \
        : "=r"((r)[0]), "=r"((r)[1]), "=r"((r)[2]), "=r"((r)[3]) : "r"(addr))
#define MMA(d, a, b0_, b1_) \
    asm volatile("mma.sync.aligned.m16n8k16.row.col.f32.f16.f16.f32 " \
        "{%0,%1,%2,%3}, {%4,%5,%6,%7}, {%8,%9}, {%0,%1,%2,%3};" \
        : "+f"((d)[0]), "+f"((d)[1]), "+f"((d)[2]), "+f"((d)[3]) \
        : "r"((a)[0]), "r"((a)[1]), "r"((a)[2]), "r"((a)[3]), "r"(b0_), "r"(b1_))

// pack 4 f32 -> 2x half2
__device__ __forceinline__ uint2 pack4h(const float* sv) {
    __half2 a = __floats2half2_rn(sv[0], sv[1]);
    __half2 b = __floats2half2_rn(sv[2], sv[3]);
    uint2 r;
    r.x = *(const uint32_t*)&a;
    r.y = *(const uint32_t*)&b;
    return r;
}

// ---------------- shared GEMM: one tap, 2-pass (Ah*Bh + Ah*Bl) --------------
// A: [128px][64c] fp16, 128B rows, SW128 at sAb (16KB).
// B: [64c][64oc] fp16, SW128; hi at sBb, lo at sBb+8192.
template<int NB>
__device__ __forceinline__ void gemm_tap(uint32_t sAb, uint32_t sBb, int lid,
                                         int mwarp, int nwarp, float acc[2][NB][4]) {
    #pragma unroll
    for (int kb = 0; kb < 4; kb++) {
        uint32_t ah[2][4];
        #pragma unroll
        for (int mb = 0; mb < 2; mb++) {
            int row = mwarp*32 + mb*16 + (lid & 15);
            uint32_t a = sAb + SWZ((uint32_t)(row*128 + (kb*16 + (lid>>4)*8)*2));
            LDSM4(ah[mb], a);
        }
        #pragma unroll
        for (int nb2 = 0; nb2 < NB/2; nb2++) {
            int k = kb*16 + (lid & 15);
            int n = nwarp*(NB*8) + nb2*16 + (lid>>4)*8;
            uint32_t b = sBb + SWZ((uint32_t)(k*128 + n*2));
            uint32_t bh[4], bl[4];
            LDSM4T(bh, b);
            LDSM4T(bl, b + 8192);
            #pragma unroll
            for (int mb = 0; mb < 2; mb++) {
                MMA(acc[mb][2*nb2],   ah[mb], bh[0], bh[1]);
                MMA(acc[mb][2*nb2],   ah[mb], bl[0], bl[1]);
                MMA(acc[mb][2*nb2+1], ah[mb], bh[2], bh[3]);
                MMA(acc[mb][2*nb2+1], ah[mb], bl[2], bl[3]);
            }
        }
    }
}

// stage one tap's weights (16KB: hi 8K + lo 8K) via cp.async
__device__ __forceinline__ void stage_b(const __half* __restrict__ wsrc, int k,
                                        uint32_t sBb, int t) {
    const char* src = (const char*)(wsrc + (size_t)k * 8192);
    #pragma unroll
    for (int i = 0; i < 4; i++)
        CP_ASYNC16(sBb + (uint32_t)(i*256 + t)*16, src + (size_t)(i*256 + t)*16);
}

// branchless bilinear sample of one tap into A buffer (fp16)
__device__ __forceinline__ void sample_dcn(const float* __restrict__ in,
                                           const float* __restrict__ offs,
                                           int by, int x0, int k,
                                           char* sm, uint32_t abuf,
                                           const int* pxv, const uint32_t* aoff,
                                           int ch4) {
    int ky = k/3 - 1, kx = k%3 - 1;
    #pragma unroll
    for (int it = 0; it < 8; it++) {
        int px = pxv[it];
        float dy = offs[px*18 + 2*k];
        float dx = offs[px*18 + 2*k + 1];
        float py  = (float)(by + ky) + dy;
        float pxf = (float)(x0 + px + kx) + dx;
        float fy = floorf(py), fx = floorf(pxf);
        float wy = py - fy, wx = pxf - fx;
        int yi = (int)fy, xi = (int)fx;
        float fy0 = (yi   >= 0 && yi   < HH) ? 1.f : 0.f;
        float fy1 = (yi+1 >= 0 && yi+1 < HH) ? 1.f : 0.f;
        float fx0 = (xi   >= 0 && xi   < WW) ? 1.f : 0.f;
        float fx1 = (xi+1 >= 0 && xi+1 < WW) ? 1.f : 0.f;
        float w00 = (1.f - wy)*(1.f - wx) * fy0 * fx0;
        float w01 = (1.f - wy)*wx         * fy0 * fx1;
        float w10 = wy*(1.f - wx)         * fy1 * fx0;
        float w11 = wy*wx                 * fy1 * fx1;
        int y0c = min(max(yi,     0), HH-1);
        int y1c = min(max(yi + 1, 0), HH-1);
        int x0c = min(max(xi,     0), WW-1);
        int x1c = min(max(xi + 1, 0), WW-1);
        const float* r0 = in + ((size_t)(y0c*WW))*64 + ch4*4;
        const float* r1 = in + ((size_t)(y1c*WW))*64 + ch4*4;
        float4 v00 = *(const float4*)(r0 + (size_t)x0c*64);
        float4 v01 = *(const float4*)(r0 + (size_t)x1c*64);
        float4 v10 = *(const float4*)(r1 + (size_t)x0c*64);
        float4 v11 = *(const float4*)(r1 + (size_t)x1c*64);
        float sv[4];
        sv[0] = w00*v00.x + w01*v01.x + w10*v10.x + w11*v11.x;
        sv[1] = w00*v00.y + w01*v01.y + w10*v10.y + w11*v11.y;
        sv[2] = w00*v00.z + w01*v01.z + w10*v10.z + w11*v11.z;
        sv[3] = w00*v00.w + w01*v01.w + w10*v10.w + w11*v11.w;
        *(uint2*)(sm + abuf + aoff[it]) = pack4h(sv);
    }
}

// branchless shifted-copy sample (offset conv A build)
__device__ __forceinline__ void sample_off(const float* __restrict__ in,
                                           int by, int x0, int k,
                                           char* sm, uint32_t abuf,
                                           const int* pxv, const uint32_t* aoff,
                                           int ch4) {
    int ky = k/3 - 1, kx = k%3 - 1;
    int yy = by + ky;
    float fv = (yy >= 0 && yy < HH) ? 1.f : 0.f;
    int yc = min(max(yy, 0), HH-1);
    const float* row = in + ((size_t)(yc*WW))*64 + ch4*4;
    #pragma unroll
    for (int it = 0; it < 8; it++) {
        int px = pxv[it];
        int xx = x0 + px + kx;
        float f = fv * ((xx >= 0 && xx < WW) ? 1.f : 0.f);
        int xc = min(max(xx, 0), WW-1);
        float4 v = *(const float4*)(row + (size_t)xc*64);
        float sv[4] = {f*v.x, f*v.y, f*v.z, f*v.w};
        *(uint2*)(sm + abuf + aoff[it]) = pack4h(sv);
    }
}

// ---------------- prep: weight split/swizzle + BN folding -------------------
__global__ void prep_kernel(
    const float* __restrict__ w1o, const float* __restrict__ w2o,
    const float* __restrict__ wd1, const float* __restrict__ wd2,
    const float* __restrict__ db1, const float* __restrict__ db2,
    const float* __restrict__ g1, const float* __restrict__ b1,
    const float* __restrict__ m1, const float* __restrict__ v1,
    const float* __restrict__ g2, const float* __restrict__ b2,
    const float* __restrict__ m2, const float* __restrict__ v2)
{
    int idx = blockIdx.x * blockDim.x + threadIdx.x;
    int nth = gridDim.x * blockDim.x;
    for (int i = idx; i < 2*9*64*64; i += nth) {
        int layer = i / 36864, r = i % 36864;
        int k = r / 4096, rr = r & 4095;
        int c = rr >> 6, oc = rr & 63;
        uint32_t sidx = SWZ((uint32_t)(c*128 + oc*2)) >> 1;
        {
            float val = (layer ? wd2 : wd1)[(oc*64 + c)*9 + k];
            __half hi = __float2half_rn(val);
            __half lo = __float2half_rn(val - __half2float(hi));
            g_wdb[layer][k][0][sidx] = hi;
            g_wdb[layer][k][1][sidx] = lo;
        }
        {
            float val = (oc < 18) ? (layer ? w2o : w1o)[(oc*64 + c)*9 + k] : 0.f;
            __half hi = __float2half_rn(val);
            __half lo = __float2half_rn(val - __half2float(hi));
            g_wob[layer][k][0][sidx] = hi;
            g_wob[layer][k][1][sidx] = lo;
        }
    }
    if (idx < 64) {
        float s = g1[idx] * rsqrtf(v1[idx] + 1e-5f);
        g_bnscale[0][idx] = s;
        g_bnshift[0][idx] = b1[idx] - m1[idx]*s + db1[idx]*s;
        float s2 = g2[idx] * rsqrtf(v2[idx] + 1e-5f);
        g_bnscale[1][idx] = s2;
        g_bnshift[1][idx] = b2[idx] - m2[idx]*s2 + db2[idx]*s2;
    }
}

// ---------------- NCHW -> NHWC ----------------------------------------------
__global__ void __launch_bounds__(256) transpose_kernel(const float* __restrict__ x) {
    __shared__ float tile[64][65];
    int p0 = blockIdx.x * 64;
    int t = threadIdx.x;
    #pragma unroll
    for (int i = 0; i < 16; i++) {
        int idx = i*256 + t;
        int c = idx >> 6, pl = idx & 63;
        tile[c][pl] = x[c*NP + p0 + pl];
    }
    __syncthreads();
    #pragma unroll
    for (int i = 0; i < 16; i++) {
        int idx = i*256 + t;
        int pl = idx >> 6, c = idx & 63;
        g_x[(p0 + pl)*64 + c] = tile[c][pl];
    }
}

// ---------------- offset conv: pipelined, double-buffered -------------------
// SMEM: A0 16K @0, A1 16K @16384, B0 16K @32768, B1 16K @49152  -> 64KB
#define OFF_SMEM 65536

__global__ void __launch_bounds__(256, 3) offconv_kernel(int layer, const float* __restrict__ bias) {
    extern __shared__ char sm[];
    const uint32_t sbase = smem_u32(sm);
    const float* __restrict__ in = layer ? g_h1 : g_x;
    const __half* __restrict__ wsrc = &g_wob[layer][0][0][0];
    const int t = threadIdx.x;
    const int wid = t >> 5, lid = t & 31;
    const int mwarp = wid & 3, nwarp = wid >> 2;
    const int by = blockIdx.x >> 2;
    const int x0 = (blockIdx.x & 3) * 128;
    const int p0 = by*WW + x0;
    const int ch4 = lid & 15;
    const int pxh = lid >> 4;

    int pxv[8];
    uint32_t aoff[8];
    #pragma unroll
    for (int it = 0; it < 8; it++) {
        pxv[it] = it*16 + wid*2 + pxh;
        aoff[it] = SWZ((uint32_t)(pxv[it]*128 + ch4*8));
    }

    stage_b(wsrc, 0, sbase + 32768, t);
    CP_COMMIT();
    sample_off(in, by, x0, 0, sm, 0, pxv, aoff, ch4);
    CP_WAIT0();
    __syncthreads();

    float acc[2][2][4] = {};
    for (int k = 0; k < 9; k++) {
        uint32_t cab = (uint32_t)(k & 1) * 16384;
        uint32_t cbb = 32768u + (uint32_t)(k & 1) * 16384;
        if (k < 8) {
            uint32_t nab = (uint32_t)((k+1) & 1) * 16384;
            uint32_t nbb = 32768u + (uint32_t)((k+1) & 1) * 16384;
            stage_b(wsrc, k+1, sbase + nbb, t);
            CP_COMMIT();
            sample_off(in, by, x0, k+1, sm, nab, pxv, aoff, ch4);
        }
        gemm_tap<2>(sbase + cab, sbase + cbb, lid, mwarp, nwarp, acc);
        CP_WAIT0();
        __syncthreads();
    }
    // epilogue: write cols < 18
    #pragma unroll
    for (int mb = 0; mb < 2; mb++) {
        int row = mwarp*32 + mb*16 + (lid >> 2);
        #pragma unroll
        for (int nb = 0; nb < 2; nb++) {
            int colb = nwarp*16 + nb*8 + (lid & 3)*2;
            if (colb < 18) {
                float b0 = bias[colb], b1v = bias[colb+1];
                float* o0 = g_off + (size_t)(p0 + row)*18 + colb;
                float* o1 = g_off + (size_t)(p0 + row + 8)*18 + colb;
                o0[0] = acc[mb][nb][0] + b0;  o0[1] = acc[mb][nb][1] + b1v;
                o1[0] = acc[mb][nb][2] + b0;  o1[1] = acc[mb][nb][3] + b1v;
            }
        }
    }
}

// ---------------- deformable conv: pipelined + BN + ReLU (+fused 1x1) -------
// SMEM: A0 16K @0, A1 16K @16384, B0 16K @32768, B1 16K @49152, offs @65536
#define DCN_SMEM 74752

template<int FUSE>
__global__ void __launch_bounds__(256, 3) dcn_kernel(int layer,
    const float* __restrict__ w1x1, const float* __restrict__ b1x1,
    float* __restrict__ out_f)
{
    extern __shared__ char sm[];
    const uint32_t sbase = smem_u32(sm);
    float* offs = (float*)(sm + 65536);
    const float* __restrict__ in = layer ? g_h1 : g_x;
    const __half* __restrict__ wsrc = &g_wdb[layer][0][0][0];
    const float* __restrict__ scl = g_bnscale[layer];
    const float* __restrict__ shf = g_bnshift[layer];
    const int t = threadIdx.x;
    const int wid = t >> 5, lid = t & 31;
    const int mwarp = wid & 3, nwarp = wid >> 2;
    const int by = blockIdx.x >> 2;
    const int x0 = (blockIdx.x & 3) * 128;
    const int p0 = by*WW + x0;
    const int ch4 = lid & 15;
    const int pxh = lid >> 4;

    int pxv[8];
    uint32_t aoff[8];
    #pragma unroll
    for (int it = 0; it < 8; it++) {
        pxv[it] = it*16 + wid*2 + pxh;
        aoff[it] = SWZ((uint32_t)(pxv[it]*128 + ch4*8));
    }

    for (int i = t; i < 2304; i += 256) offs[i] = g_off[(size_t)p0*18 + i];
    __syncthreads();   // offs ready

    stage_b(wsrc, 0, sbase + 32768, t);
    CP_COMMIT();
    sample_dcn(in, offs, by, x0, 0, sm, 0, pxv, aoff, ch4);
    CP_WAIT0();
    __syncthreads();

    float acc[2][4][4] = {};
    for (int k = 0; k < 9; k++) {
        uint32_t cab = (uint32_t)(k & 1) * 16384;
        uint32_t cbb = 32768u + (uint32_t)(k & 1) * 16384;
        if (k < 8) {
            uint32_t nab = (uint32_t)((k+1) & 1) * 16384;
            uint32_t nbb = 32768u + (uint32_t)((k+1) & 1) * 16384;
            stage_b(wsrc, k+1, sbase + nbb, t);
            CP_COMMIT();
            sample_dcn(in, offs, by, x0, k+1, sm, nab, pxv, aoff, ch4);
        }
        gemm_tap<4>(sbase + cab, sbase + cbb, lid, mwarp, nwarp, acc);
        CP_WAIT0();
        __syncthreads();
    }

    if (!FUSE) {
        #pragma unroll
        for (int mb = 0; mb < 2; mb++) {
            int row = mwarp*32 + mb*16 + (lid >> 2);
            #pragma unroll
            for (int nb = 0; nb < 4; nb++) {
                int colb = nwarp*32 + nb*8 + (lid & 3)*2;
                float s0 = scl[colb], s1 = scl[colb+1];
                float h0 = shf[colb], h1v = shf[colb+1];
                float v00 = fmaxf(acc[mb][nb][0]*s0 + h0, 0.f);
                float v01 = fmaxf(acc[mb][nb][1]*s1 + h1v, 0.f);
                float v10 = fmaxf(acc[mb][nb][2]*s0 + h0, 0.f);
                float v11 = fmaxf(acc[mb][nb][3]*s1 + h1v, 0.f);
                *(float2*)(g_h1 + (size_t)(p0 + row)*64 + colb)     = make_float2(v00, v01);
                *(float2*)(g_h1 + (size_t)(p0 + row + 8)*64 + colb) = make_float2(v10, v11);
            }
        }
    } else {
        float pa[2] = {0.f, 0.f}, pb[2] = {0.f, 0.f};
        #pragma unroll
        for (int mb = 0; mb < 2; mb++) {
            #pragma unroll
            for (int nb = 0; nb < 4; nb++) {
                int colb = nwarp*32 + nb*8 + (lid & 3)*2;
                float s0 = scl[colb], s1 = scl[colb+1];
                float h0 = shf[colb], h1v = shf[colb+1];
                float w0 = w1x1[colb], w1 = w1x1[colb+1];
                float v00 = fmaxf(acc[mb][nb][0]*s0 + h0, 0.f);
                float v01 = fmaxf(acc[mb][nb][1]*s1 + h1v, 0.f);
                float v10 = fmaxf(acc[mb][nb][2]*s0 + h0, 0.f);
                float v11 = fmaxf(acc[mb][nb][3]*s1 + h1v, 0.f);
                pa[mb] += v00*w0 + v01*w1;
                pb[mb] += v10*w0 + v11*w1;
            }
            pa[mb] += __shfl_xor_sync(0xffffffffu, pa[mb], 1);
            pa[mb] += __shfl_xor_sync(0xffffffffu, pa[mb], 2);
            pb[mb] += __shfl_xor_sync(0xffffffffu, pb[mb], 1);
            pb[mb] += __shfl_xor_sync(0xffffffffu, pb[mb], 2);
        }
        float* red = (float*)(sm + 65536);   // offs no longer needed
        if ((lid & 3) == 0) {
            #pragma unroll
            for (int mb = 0; mb < 2; mb++) {
                int row = mwarp*32 + mb*16 + (lid >> 2);
                red[nwarp*128 + row]     = pa[mb];
                red[nwarp*128 + row + 8] = pb[mb];
            }
        }
        __syncthreads();
        if (t < 128) out_f[p0 + t] = red[t] + red[128 + t] + b1x1[0];
    }
}

// ---------------- launch -----------------------------------------------------
extern "C" void kernel_launch(void* const* d_in, const int* in_sizes, int n_in,
                              void* d_out, int out_size) {
    const float* x    = (const float*)d_in[0];
    const float* w1o  = (const float*)d_in[1];
    const float* b1o  = (const float*)d_in[2];
    const float* wd1  = (const float*)d_in[3];
    const float* db1  = (const float*)d_in[4];
    const float* g1   = (const float*)d_in[5];
    const float* be1  = (const float*)d_in[6];
    const float* m1   = (const float*)d_in[7];
    const float* v1   = (const float*)d_in[8];
    const float* w2o  = (const float*)d_in[9];
    const float* b2o  = (const float*)d_in[10];
    const float* wd2  = (const float*)d_in[11];
    const float* db2  = (const float*)d_in[12];
    const float* g2   = (const float*)d_in[13];
    const float* be2  = (const float*)d_in[14];
    const float* m2   = (const float*)d_in[15];
    const float* v2   = (const float*)d_in[16];
    const float* wc   = (const float*)d_in[17];
    const float* bc   = (const float*)d_in[18];
    float* out = (float*)d_out;

    cudaFuncSetAttribute(offconv_kernel, cudaFuncAttributeMaxDynamicSharedMemorySize, OFF_SMEM);
    cudaFuncSetAttribute(dcn_kernel<0>,  cudaFuncAttributeMaxDynamicSharedMemorySize, DCN_SMEM);
    cudaFuncSetAttribute(dcn_kernel<1>,  cudaFuncAttributeMaxDynamicSharedMemorySize, DCN_SMEM);

    prep_kernel<<<64, 256>>>(w1o, w2o, wd1, wd2, db1, db2,
                             g1, be1, m1, v1, g2, be2, m2, v2);
    transpose_kernel<<<NP/64, 256>>>(x);
    offconv_kernel<<<2048, 256, OFF_SMEM>>>(0, b1o);
    dcn_kernel<0><<<2048, 256, DCN_SMEM>>>(0, nullptr, nullptr, nullptr);
    offconv_kernel<<<2048, 256, OFF_SMEM>>>(1, b2o);
    dcn_kernel<1><<<2048, 256, DCN_SMEM>>>(1, wc, bc, out);
}